// round 8
// baseline (speedup 1.0000x reference)
#include <cuda_runtime.h>
#include <math.h>

#define BB 4
#define TT 512
#define FF 257
#define FPI 258              // padded in_s row (even -> 8B-aligned f-pairs)
#define DD 128
#define C2P 20
#define NLN (DD*FF)          // 32896
#define NTH 512

typedef unsigned long long ull;

__device__ __forceinline__ void fma2(ull &acc, ull a, ull b) {
    asm("fma.rn.f32x2 %0, %1, %2, %0;" : "+l"(acc) : "l"(a), "l"(b));
}
__device__ __forceinline__ float2 unpack2(ull v) {
    unsigned lo, hi;
    asm("mov.b64 {%0, %1}, %2;" : "=r"(lo), "=r"(hi) : "l"(v));
    return make_float2(__uint_as_float(lo), __uint_as_float(hi));
}

// ---------------- device scratch ----------------
__device__ float g_xs[(size_t)BB*TT*C2P*FF];   // features [B][T][C][F]
__device__ float g_mean[BB*FF*8];
__device__ float g_inv[BB*FF];
__device__ ull   g_wt2[100*DD];                // transposed weights [j][d], dup-packed

// ---------------- K0: weight transpose + pack ----------------
__global__ void wtrans_kernel(const float* __restrict__ conv_w) {
    for (int i = threadIdx.x; i < DD * 100; i += blockDim.x) {
        int d = i / 100, j = i - d * 100;
        unsigned u = __float_as_uint(conv_w[i]);
        ull r;
        asm("mov.b64 %0, {%1, %1};" : "=l"(r) : "r"(u));
        g_wt2[j * DD + d] = r;
    }
}

// ---------------- K1: time stats, one block per (b,f) ----------------
__global__ void stats_kernel(const float* __restrict__ x) {
    int b = blockIdx.x;
    int f = blockIdx.y;
    int tid = threadIdx.x;          // 256
    int ch = tid & 7;
    int tl = tid >> 3;

    float s = 0.f, q = 0.f;
    const float* px = x + ((size_t)b * TT * FF + f) * 8 + ch;
    #pragma unroll 4
    for (int t = tl; t < TT; t += 32) {
        float v = px[(size_t)t * FF * 8];
        s += v; q += v * v;
    }
    s += __shfl_xor_sync(0xffffffffu, s, 8);
    q += __shfl_xor_sync(0xffffffffu, q, 8);
    s += __shfl_xor_sync(0xffffffffu, s, 16);
    q += __shfl_xor_sync(0xffffffffu, q, 16);

    __shared__ float sb[8][8], qb[8][8];
    int warp = tid >> 5, lane = tid & 31;
    if (lane < 8) { sb[warp][lane] = s; qb[warp][lane] = q; }
    __syncthreads();

    if (tid == 0) {
        const float invT = 1.0f / (float)TT;
        float ssum[8], qsum[8];
        #pragma unroll
        for (int c = 0; c < 8; c++) {
            float a = 0.f, bq = 0.f;
            #pragma unroll
            for (int w = 0; w < 8; w++) { a += sb[w][c]; bq += qb[w][c]; }
            ssum[c] = a * invT; qsum[c] = bq * invT;
        }
        float tot = 0.f;
        #pragma unroll
        for (int m = 0; m < 4; m++) {
            float mr = ssum[m], mi = ssum[m + 4];
            tot += qsum[m] + qsum[m + 4] - mr * mr - mi * mi;
        }
        #pragma unroll
        for (int j = 0; j < 8; j++) g_mean[(b * FF + f) * 8 + j] = ssum[j];
        g_inv[b * FF + f] = rsqrtf(fmaxf(tot, 1e-10f));
    }
}

// ---------------- K2: SCM pair features ----------------
__global__ void feat_kernel(const float* __restrict__ x,
                            const float* __restrict__ expo,
                            const float* __restrict__ ipd) {
    int bt = blockIdx.x;
    int b  = bt / TT;

    for (int f = threadIdx.x; f < FF; f += blockDim.x) {
        const float* px = x + ((size_t)bt * FF + f) * 8;
        const float* mn = g_mean + (b * FF + f) * 8;
        float inv = g_inv[b * FF + f];

        float vr[4], vi[4];
        #pragma unroll
        for (int m = 0; m < 4; m++) {
            vr[m] = (px[m]     - mn[m])     * inv;
            vi[m] = (px[m + 4] - mn[m + 4]) * inv;
        }
        float s1 = 1.0f / (1.0f + expf(-expo[f]));
        float s2 = 1.0f / (1.0f + expf(-ipd[f]));

        const int ia[10] = {0,0,0,0,1,1,1,2,2,3};
        const int ja[10] = {0,1,2,3,1,2,3,2,3,3};
        float* ob = g_xs + (size_t)bt * C2P * FF + f;

        #pragma unroll
        for (int p = 0; p < 10; p++) {
            float re = vr[ia[p]] * vr[ja[p]] + vi[ia[p]] * vi[ja[p]];
            float im = vi[ia[p]] * vr[ja[p]] - vr[ia[p]] * vi[ja[p]];
            float a  = sqrtf(re * re + im * im);
            float beta = (a > 0.f) ? exp2f(s1 * log2f(a)) : 0.f;
            float mag  = a / (beta + 1e-10f);
            float ang  = atan2f(im, re) * s2;
            float sn, cs;
            sincosf(ang, &sn, &cs);
            ob[(size_t)(2 * p)     * FF] = mag * cs;
            ob[(size_t)(2 * p + 1) * FF] = mag * sn;
        }
    }
}

// ---------------- K3: fused conv1d (SAME,K=5) + LayerNorm ----------------
// 512 threads: warp w -> d rows [8w,8w+8); lane -> f-pairs {2*lane,2*lane+1}+64u.
// Weights pre-packed as f32x2 in smem: LDS.128 broadcast -> 2 W regs, no movs.
extern __shared__ float smem[];

__global__ void __launch_bounds__(NTH, 1)
conv_ln_kernel(const float* __restrict__ conv_b,
               const float* __restrict__ ln_w,
               const float* __restrict__ ln_b,
               float* __restrict__ out) {
    int bt = blockIdx.x;
    int b  = bt / TT;
    int t  = bt % TT;
    int tid = threadIdx.x;
    int warp = tid >> 5, lane = tid & 31;
    int d0 = warp * 8;

    ull*   w_s  = (ull*)smem;                    // 100*128 ull = 102,400 B
    float* in_s = (float*)(w_s + 100 * DD);      // 100*258 fl  = 103,200 B
    float* red  = in_s + 100 * FPI;              // 40 fl

    // stage packed weights (coalesced 8B)
    for (int i = tid; i < 100 * DD; i += NTH) w_s[i] = g_wt2[i];

    // stage input rows, division-free: warp per row, lanes stride f
    for (int kc = warp; kc < 100; kc += 16) {
        int c = kc / 5;
        int k = kc - c * 5;
        int tt = t + k - 2;
        float* dst = in_s + kc * FPI;
        if (tt >= 0 && tt < TT) {
            const float* src = g_xs + ((size_t)(b * TT + tt) * C2P + c) * FF;
            for (int fl = lane; fl < FF; fl += 32) dst[fl] = src[fl];
        } else {
            for (int fl = lane; fl < FF; fl += 32) dst[fl] = 0.f;
        }
        if (lane == 0) dst[FF] = 0.f;
    }
    __syncthreads();

    // acc[dd][u]: packed y for d=d0+dd, f = {2*lane, 2*lane+1} + 64u
    ull acc[8][4];
    #pragma unroll
    for (int dd = 0; dd < 8; dd++)
        #pragma unroll
        for (int u = 0; u < 4; u++) acc[dd][u] = 0ull;

    const ull* rowbase = (const ull*)in_s + lane;   // f-pair index = lane + 32u
    const ulonglong2* wbase = (const ulonglong2*)(w_s + d0);

    #pragma unroll 2
    for (int j = 0; j < 100; j++) {
        const ull* rp = rowbase + j * (FPI / 2);
        ull X0 = rp[0], X1 = rp[32], X2 = rp[64], X3 = rp[96];

        const ulonglong2* wp = wbase + j * (DD / 2);
        // first 4 d rows
        ulonglong2 wA = wp[0], wB = wp[1];
        fma2(acc[0][0], wA.x, X0); fma2(acc[0][1], wA.x, X1); fma2(acc[0][2], wA.x, X2); fma2(acc[0][3], wA.x, X3);
        fma2(acc[1][0], wA.y, X0); fma2(acc[1][1], wA.y, X1); fma2(acc[1][2], wA.y, X2); fma2(acc[1][3], wA.y, X3);
        fma2(acc[2][0], wB.x, X0); fma2(acc[2][1], wB.x, X1); fma2(acc[2][2], wB.x, X2); fma2(acc[2][3], wB.x, X3);
        fma2(acc[3][0], wB.y, X0); fma2(acc[3][1], wB.y, X1); fma2(acc[3][2], wB.y, X2); fma2(acc[3][3], wB.y, X3);
        // second 4 d rows
        ulonglong2 wC = wp[2], wD = wp[3];
        fma2(acc[4][0], wC.x, X0); fma2(acc[4][1], wC.x, X1); fma2(acc[4][2], wC.x, X2); fma2(acc[4][3], wC.x, X3);
        fma2(acc[5][0], wC.y, X0); fma2(acc[5][1], wC.y, X1); fma2(acc[5][2], wC.y, X2); fma2(acc[5][3], wC.y, X3);
        fma2(acc[6][0], wD.x, X0); fma2(acc[6][1], wD.x, X1); fma2(acc[6][2], wD.x, X2); fma2(acc[6][3], wD.x, X3);
        fma2(acc[7][0], wD.y, X0); fma2(acc[7][1], wD.y, X1); fma2(acc[7][2], wD.y, X2); fma2(acc[7][3], wD.y, X3);
    }

    // tail column f = 256: lanes split j, warp-reduce
    float acct[8];
    #pragma unroll
    for (int dd = 0; dd < 8; dd++) acct[dd] = 0.f;
    for (int jj = lane; jj < 100; jj += 32) {
        float xv = in_s[jj * FPI + 256];
        const ull* wj = w_s + jj * DD + d0;
        #pragma unroll
        for (int dd = 0; dd < 8; dd++) {
            float wv = __uint_as_float((unsigned)(wj[dd] & 0xffffffffull));
            acct[dd] = fmaf(wv, xv, acct[dd]);
        }
    }
    #pragma unroll
    for (int dd = 0; dd < 8; dd++) {
        #pragma unroll
        for (int o = 16; o > 0; o >>= 1)
            acct[dd] += __shfl_xor_sync(0xffffffffu, acct[dd], o);
    }

    const float4* bp = (const float4*)(conv_b + d0);
    float4 b4a = bp[0], b4b = bp[1];
    float bias[8] = {b4a.x, b4a.y, b4a.z, b4a.w, b4b.x, b4b.y, b4b.z, b4b.w};
    #pragma unroll
    for (int dd = 0; dd < 8; dd++) acct[dd] += bias[dd];

    // LN stats straight from packed accumulators (+bias on the fly)
    float s = 0.f, q = 0.f;
    #pragma unroll
    for (int dd = 0; dd < 8; dd++) {
        #pragma unroll
        for (int u = 0; u < 4; u++) {
            float2 pr = unpack2(acc[dd][u]);
            float v0 = pr.x + bias[dd], v1 = pr.y + bias[dd];
            s += v0 + v1; q += v0 * v0 + v1 * v1;
        }
    }
    if (lane == 0) {
        #pragma unroll
        for (int dd = 0; dd < 8; dd++) { s += acct[dd]; q += acct[dd] * acct[dd]; }
    }
    #pragma unroll
    for (int o = 16; o > 0; o >>= 1) {
        s += __shfl_xor_sync(0xffffffffu, s, o);
        q += __shfl_xor_sync(0xffffffffu, q, o);
    }
    if (lane == 0) { red[warp] = s; red[16 + warp] = q; }
    __syncthreads();
    if (tid < 32) {
        s = (tid < 16) ? red[tid] : 0.f;
        q = (tid < 16) ? red[16 + tid] : 0.f;
        #pragma unroll
        for (int o = 8; o > 0; o >>= 1) {
            s += __shfl_xor_sync(0xffffffffu, s, o);
            q += __shfl_xor_sync(0xffffffffu, q, o);
        }
        if (tid == 0) {
            const float invN = 1.0f / (float)NLN;
            float mu  = s * invN;
            float var = q * invN - mu * mu;
            red[32] = mu;
            red[33] = rsqrtf(var + 1e-5f);
        }
    }
    __syncthreads();
    float mu = red[32], rs = red[33];

    // normalize + store (scalar: d*257 row base can be odd)
    float* po = out + (size_t)bt * NLN;
    #pragma unroll
    for (int dd = 0; dd < 8; dd++) {
        int rowo = (d0 + dd) * FF;
        #pragma unroll
        for (int u = 0; u < 4; u++) {
            int oi = rowo + 2 * lane + 64 * u;
            float2 pr = unpack2(acc[dd][u]);
            po[oi]     = (pr.x + bias[dd] - mu) * rs * ln_w[oi]     + ln_b[oi];
            po[oi + 1] = (pr.y + bias[dd] - mu) * rs * ln_w[oi + 1] + ln_b[oi + 1];
        }
        if (lane == 0) {
            int oi = rowo + 256;
            po[oi] = (acct[dd] - mu) * rs * ln_w[oi] + ln_b[oi];
        }
    }
}

// ---------------- launch ----------------
extern "C" void kernel_launch(void* const* d_in, const int* in_sizes, int n_in,
                              void* d_out, int out_size) {
    const float* x    = (const float*)d_in[0];
    const float* expo = (const float*)d_in[1];
    const float* ipd  = (const float*)d_in[2];
    const float* cw   = (const float*)d_in[3];
    const float* cb   = (const float*)d_in[4];
    const float* lw   = (const float*)d_in[5];
    const float* lb   = (const float*)d_in[6];
    float* out = (float*)d_out;

    wtrans_kernel<<<1, 256>>>(cw);
    stats_kernel<<<dim3(BB, FF), 256>>>(x);
    feat_kernel<<<BB * TT, 256>>>(x, expo, ipd);

    int smem_bytes = 100 * DD * 8 + (100 * FPI + 40) * (int)sizeof(float); // 205,760 B
    cudaFuncSetAttribute(conv_ln_kernel,
                         cudaFuncAttributeMaxDynamicSharedMemorySize, smem_bytes);
    conv_ln_kernel<<<BB * TT, NTH, smem_bytes>>>(cb, lw, lb, out);
}

// round 10
// speedup vs baseline: 1.1322x; 1.1322x over previous
#include <cuda_runtime.h>
#include <cuda_bf16.h>
#include <math.h>
#include <stdint.h>

#define BB 4
#define TT 512
#define FF 257
#define DD 128
#define C2P 20
#define NLN (DD*FF)
#define NTH 512

#define KP   112           // padded k (7 tiles of 16)
#define WSP  120           // A pitch (bf16): 240B = 15*16B -> distinct ldmatrix banks
#define BSP  296           // B pitch (bf16): 592B = 37*16B -> distinct ldmatrix banks
#define NFP  288           // padded f (36 n-tiles of 8)

// smem byte offsets
#define WS_HI 0
#define WS_LO (WS_HI + 128*WSP*2)      // 30720
#define BS_HI (WS_LO + 128*WSP*2)      // 61440
#define BS_LO (BS_HI + KP*BSP*2)       // 127744
#define SRED  (BS_LO + KP*BSP*2)       // 194048
#define SM_TOTAL (SRED + 160)          // 194208

#define LDSM4(r0,r1,r2,r3,addr) \
  asm volatile("ldmatrix.sync.aligned.m8n8.x4.shared.b16 {%0,%1,%2,%3}, [%4];" \
    : "=r"(r0),"=r"(r1),"=r"(r2),"=r"(r3) : "r"(addr))
#define LDSM2T(r0,r1,addr) \
  asm volatile("ldmatrix.sync.aligned.m8n8.x2.trans.shared.b16 {%0,%1}, [%2];" \
    : "=r"(r0),"=r"(r1) : "r"(addr))
#define MMABF16(c,a,b0,b1) \
  asm volatile("mma.sync.aligned.m16n8k16.row.col.f32.bf16.bf16.f32 " \
    "{%0,%1,%2,%3}, {%4,%5,%6,%7}, {%8,%9}, {%0,%1,%2,%3};" \
    : "+f"((c)[0]),"+f"((c)[1]),"+f"((c)[2]),"+f"((c)[3]) \
    : "r"((a)[0]),"r"((a)[1]),"r"((a)[2]),"r"((a)[3]),"r"(b0),"r"(b1))

__device__ __forceinline__ uint32_t smem_u32(const void* p) {
    uint32_t a;
    asm("{ .reg .u64 t; cvta.to.shared.u64 t, %1; cvt.u32.u64 %0, t; }" : "=r"(a) : "l"(p));
    return a;
}

// ---------------- device scratch ----------------
__device__ float g_xs[(size_t)BB*TT*C2P*FF];        // features [B][T][C][F]
__device__ float g_mean[BB*FF*8];
__device__ float g_inv[BB*FF];
__device__ __nv_bfloat16 g_wa_hi[128*WSP];          // W hi/lo, [d][k], zero-padded
__device__ __nv_bfloat16 g_wa_lo[128*WSP];

// ---------------- K0: weight split ----------------
__global__ void wsplit_kernel(const float* __restrict__ conv_w) {
    for (int i = threadIdx.x; i < 128*100; i += blockDim.x) {
        int d = i / 100, j = i - d*100;
        float v = conv_w[i];
        __nv_bfloat16 h = __float2bfloat16(v);
        __nv_bfloat16 l = __float2bfloat16(v - __bfloat162float(h));
        g_wa_hi[d*WSP + j] = h;
        g_wa_lo[d*WSP + j] = l;
    }
}

// ---------------- K1: time stats ----------------
__global__ void stats_kernel(const float* __restrict__ x) {
    int b = blockIdx.x;
    int f = blockIdx.y;
    int tid = threadIdx.x;
    int ch = tid & 7;
    int tl = tid >> 3;

    float s = 0.f, q = 0.f;
    const float* px = x + ((size_t)b * TT * FF + f) * 8 + ch;
    #pragma unroll 4
    for (int t = tl; t < TT; t += 32) {
        float v = px[(size_t)t * FF * 8];
        s += v; q += v * v;
    }
    s += __shfl_xor_sync(0xffffffffu, s, 8);
    q += __shfl_xor_sync(0xffffffffu, q, 8);
    s += __shfl_xor_sync(0xffffffffu, s, 16);
    q += __shfl_xor_sync(0xffffffffu, q, 16);

    __shared__ float sb[8][8], qb[8][8];
    int warp = tid >> 5, lane = tid & 31;
    if (lane < 8) { sb[warp][lane] = s; qb[warp][lane] = q; }
    __syncthreads();

    if (tid == 0) {
        const float invT = 1.0f / (float)TT;
        float ssum[8], qsum[8];
        #pragma unroll
        for (int c = 0; c < 8; c++) {
            float a = 0.f, bq = 0.f;
            #pragma unroll
            for (int w = 0; w < 8; w++) { a += sb[w][c]; bq += qb[w][c]; }
            ssum[c] = a * invT; qsum[c] = bq * invT;
        }
        float tot = 0.f;
        #pragma unroll
        for (int m = 0; m < 4; m++) {
            float mr = ssum[m], mi = ssum[m + 4];
            tot += qsum[m] + qsum[m + 4] - mr * mr - mi * mi;
        }
        #pragma unroll
        for (int j = 0; j < 8; j++) g_mean[(b * FF + f) * 8 + j] = ssum[j];
        g_inv[b * FF + f] = rsqrtf(fmaxf(tot, 1e-10f));
    }
}

// ---------------- K2: SCM pair features ----------------
__global__ void feat_kernel(const float* __restrict__ x,
                            const float* __restrict__ expo,
                            const float* __restrict__ ipd) {
    int bt = blockIdx.x;
    int b  = bt / TT;

    for (int f = threadIdx.x; f < FF; f += blockDim.x) {
        const float* px = x + ((size_t)bt * FF + f) * 8;
        const float* mn = g_mean + (b * FF + f) * 8;
        float inv = g_inv[b * FF + f];

        float vr[4], vi[4];
        #pragma unroll
        for (int m = 0; m < 4; m++) {
            vr[m] = (px[m]     - mn[m])     * inv;
            vi[m] = (px[m + 4] - mn[m + 4]) * inv;
        }
        float s1 = 1.0f / (1.0f + expf(-expo[f]));
        float s2 = 1.0f / (1.0f + expf(-ipd[f]));

        const int ia[10] = {0,0,0,0,1,1,1,2,2,3};
        const int ja[10] = {0,1,2,3,1,2,3,2,3,3};
        float* ob = g_xs + (size_t)bt * C2P * FF + f;

        #pragma unroll
        for (int p = 0; p < 10; p++) {
            float re = vr[ia[p]] * vr[ja[p]] + vi[ia[p]] * vi[ja[p]];
            float im = vi[ia[p]] * vr[ja[p]] - vr[ia[p]] * vi[ja[p]];
            float a  = sqrtf(re * re + im * im);
            float beta = (a > 0.f) ? exp2f(s1 * log2f(a)) : 0.f;
            float mag  = a / (beta + 1e-10f);
            float ang  = atan2f(im, re) * s2;
            float sn, cs;
            sincosf(ang, &sn, &cs);
            ob[(size_t)(2 * p)     * FF] = mag * cs;
            ob[(size_t)(2 * p + 1) * FF] = mag * sn;
        }
    }
}

// ---------------- K3: HMMA bf16-split conv + LayerNorm ----------------
// 16 warps = 4 m-groups (32 d rows) x 4 n-groups (9 n-tiles of 8 f).
// Y = Whi*Xhi + Whi*Xlo + Wlo*Xhi (fp32 accum), D in registers, LN fused.
extern __shared__ char sm[];

__global__ void __launch_bounds__(NTH, 1)
conv_ln_kernel(const float* __restrict__ conv_b,
               const float* __restrict__ ln_w,
               const float* __restrict__ ln_b,
               float* __restrict__ out) {
    int bt = blockIdx.x;
    int b  = bt / TT;
    int t  = bt % TT;
    int tid = threadIdx.x;
    int warp = tid >> 5, lane = tid & 31;
    int g = lane >> 2, tg = lane & 3;
    int mg = warp & 3;          // d rows [32mg, 32mg+32)
    int ng = warp >> 2;         // f cols [72ng, 72ng+72)

    // ---- stage A (copy prebuilt hi/lo, coalesced u32) ----
    {
        const uint32_t* sh = (const uint32_t*)g_wa_hi;
        const uint32_t* sl = (const uint32_t*)g_wa_lo;
        uint32_t* dh = (uint32_t*)(sm + WS_HI);
        uint32_t* dl = (uint32_t*)(sm + WS_LO);
        for (int i = tid; i < 128*WSP/2; i += NTH) { dh[i] = sh[i]; dl[i] = sl[i]; }
    }

    // ---- stage B k-major [k][f]: warp per k-row, lane packs 2 f values ----
    for (int j = warp; j < KP; j += 16) {
        int c = j / 5, k = j - c * 5;
        int tt = t + k - 2;
        bool jv = (j < 100) && (tt >= 0) && (tt < TT);
        const float* src = jv ? (g_xs + ((size_t)(b*TT + tt)*C2P + c)*FF) : (const float*)0;
        uint32_t* rh = (uint32_t*)(sm + BS_HI) + j * (BSP/2);
        uint32_t* rl = (uint32_t*)(sm + BS_LO) + j * (BSP/2);
        for (int fp = lane; fp < NFP/2; fp += 32) {
            int f0 = 2*fp;
            float v0 = (jv && f0     < FF) ? src[f0]     : 0.f;
            float v1 = (jv && f0 + 1 < FF) ? src[f0 + 1] : 0.f;
            __nv_bfloat16 h0 = __float2bfloat16(v0);
            __nv_bfloat16 h1 = __float2bfloat16(v1);
            __nv_bfloat16 l0 = __float2bfloat16(v0 - __bfloat162float(h0));
            __nv_bfloat16 l1 = __float2bfloat16(v1 - __bfloat162float(h1));
            rh[fp] = (uint32_t)__bfloat16_as_ushort(h0) | ((uint32_t)__bfloat16_as_ushort(h1) << 16);
            rl[fp] = (uint32_t)__bfloat16_as_ushort(l0) | ((uint32_t)__bfloat16_as_ushort(l1) << 16);
        }
    }
    __syncthreads();

    // ---- mainloop ----
    float acc[2][9][4];
    #pragma unroll
    for (int mt = 0; mt < 2; mt++)
        #pragma unroll
        for (int nt = 0; nt < 9; nt++)
            #pragma unroll
            for (int ci = 0; ci < 4; ci++) acc[mt][nt][ci] = 0.f;

    uint32_t sb = smem_u32(sm);
    int aRow = (lane & 7) + 8 * ((lane >> 3) & 1);   // ldmatrix x4 row mapping
    int aK   = (lane >> 4) * 8;
    uint32_t aoff = sb + WS_HI + (uint32_t)(((32*mg + aRow) * WSP + aK) * 2);
    uint32_t boff = sb + BS_HI + (uint32_t)((aRow * BSP + 72*ng) * 2);  // lanes 16-31 mirror 0-15 (x2 ignores)

    for (int kt = 0; kt < 7; kt++) {
        uint32_t ah[2][4], al[2][4];
        #pragma unroll
        for (int mt = 0; mt < 2; mt++) {
            uint32_t a = aoff + mt * (16*WSP*2) + kt * 32;
            LDSM4(ah[mt][0], ah[mt][1], ah[mt][2], ah[mt][3], a);
            LDSM4(al[mt][0], al[mt][1], al[mt][2], al[mt][3], a + (WS_LO - WS_HI));
        }
        #pragma unroll
        for (int nt = 0; nt < 9; nt++) {
            uint32_t badr = boff + kt * (16*BSP*2) + nt * 16;
            uint32_t bh0, bh1, bl0, bl1;
            LDSM2T(bh0, bh1, badr);
            LDSM2T(bl0, bl1, badr + (BS_LO - BS_HI));
            #pragma unroll
            for (int mt = 0; mt < 2; mt++) {
                MMABF16(acc[mt][nt], ah[mt], bh0, bh1);
                MMABF16(acc[mt][nt], ah[mt], bl0, bl1);
                MMABF16(acc[mt][nt], al[mt], bh0, bh1);
            }
        }
    }

    // ---- bias ----
    float bias[2][2];
    #pragma unroll
    for (int mt = 0; mt < 2; mt++) {
        int r = 32*mg + 16*mt + g;
        bias[mt][0] = conv_b[r];
        bias[mt][1] = conv_b[r + 8];
    }

    // ---- LN stats from registers ----
    float* red = (float*)(sm + SRED);
    float s = 0.f, q = 0.f;
    #pragma unroll
    for (int mt = 0; mt < 2; mt++)
        #pragma unroll
        for (int nt = 0; nt < 9; nt++) {
            int fb = 72*ng + 8*nt + 2*tg;
            if (fb < FF) {
                float v0 = acc[mt][nt][0] + bias[mt][0];
                float v2 = acc[mt][nt][2] + bias[mt][1];
                s += v0 + v2; q += v0*v0 + v2*v2;
            }
            if (fb + 1 < FF) {
                float v1 = acc[mt][nt][1] + bias[mt][0];
                float v3 = acc[mt][nt][3] + bias[mt][1];
                s += v1 + v3; q += v1*v1 + v3*v3;
            }
        }
    #pragma unroll
    for (int o = 16; o > 0; o >>= 1) {
        s += __shfl_xor_sync(0xffffffffu, s, o);
        q += __shfl_xor_sync(0xffffffffu, q, o);
    }
    if (lane == 0) { red[warp] = s; red[16 + warp] = q; }
    __syncthreads();
    if (tid < 32) {
        s = (tid < 16) ? red[tid] : 0.f;
        q = (tid < 16) ? red[16 + tid] : 0.f;
        #pragma unroll
        for (int o = 8; o > 0; o >>= 1) {
            s += __shfl_xor_sync(0xffffffffu, s, o);
            q += __shfl_xor_sync(0xffffffffu, q, o);
        }
        if (tid == 0) {
            const float invN = 1.0f / (float)NLN;
            float mu  = s * invN;
            float var = q * invN - mu * mu;
            red[32] = mu;
            red[33] = rsqrtf(var + 1e-5f);
        }
    }
    __syncthreads();
    float mu = red[32], rs = red[33];

    // ---- normalize + store ----
    float* po = out + (size_t)bt * NLN;
    #pragma unroll
    for (int mt = 0; mt < 2; mt++) {
        int r0 = (32*mg + 16*mt + g) * FF;
        int r1 = r0 + 8 * FF;
        #pragma unroll
        for (int nt = 0; nt < 9; nt++) {
            int fb = 72*ng + 8*nt + 2*tg;
            if (fb < FF) {
                int o0 = r0 + fb, o1 = r1 + fb;
                po[o0] = (acc[mt][nt][0] + bias[mt][0] - mu) * rs * ln_w[o0] + ln_b[o0];
                po[o1] = (acc[mt][nt][2] + bias[mt][1] - mu) * rs * ln_w[o1] + ln_b[o1];
            }
            if (fb + 1 < FF) {
                int o0 = r0 + fb + 1, o1 = r1 + fb + 1;
                po[o0] = (acc[mt][nt][1] + bias[mt][0] - mu) * rs * ln_w[o0] + ln_b[o0];
                po[o1] = (acc[mt][nt][3] + bias[mt][1] - mu) * rs * ln_w[o1] + ln_b[o1];
            }
        }
    }
}

// ---------------- launch ----------------
extern "C" void kernel_launch(void* const* d_in, const int* in_sizes, int n_in,
                              void* d_out, int out_size) {
    const float* x    = (const float*)d_in[0];
    const float* expo = (const float*)d_in[1];
    const float* ipd  = (const float*)d_in[2];
    const float* cw   = (const float*)d_in[3];
    const float* cb   = (const float*)d_in[4];
    const float* lw   = (const float*)d_in[5];
    const float* lb   = (const float*)d_in[6];
    float* out = (float*)d_out;

    wsplit_kernel<<<1, 256>>>(cw);
    stats_kernel<<<dim3(BB, FF), 256>>>(x);
    feat_kernel<<<BB * TT, 256>>>(x, expo, ipd);

    cudaFuncSetAttribute(conv_ln_kernel,
                         cudaFuncAttributeMaxDynamicSharedMemorySize, SM_TOTAL);
    conv_ln_kernel<<<BB * TT, NTH, SM_TOTAL>>>(cb, lw, lb, out);
}

// round 11
// speedup vs baseline: 1.1581x; 1.0229x over previous
#include <cuda_runtime.h>
#include <cuda_bf16.h>
#include <math.h>
#include <stdint.h>

#define BB 4
#define TT 512
#define FF 257
#define DD 128
#define C2P 20
#define NLN (DD*FF)
#define NTH 768

#define KP   112           // padded k (7 tiles of 16)
#define WSP  120           // A pitch (bf16): 240B rows -> conflict-free ldmatrix
#define BSP  264           // B pitch (bf16): 528B rows -> conflict-free ldmatrix
#define NFP  264           // padded f (33 n-tiles of 8)

// smem byte offsets
#define WS_HI 0
#define WS_LO (WS_HI + 128*WSP*2)      // 30720
#define BS_HI (WS_LO + 128*WSP*2)      // 61440
#define BS_LO (BS_HI + KP*BSP*2)       // 120576
#define SRED  (BS_LO + KP*BSP*2)       // 179712
#define SM_TOTAL (SRED + 224)

#define LDSM4(r0,r1,r2,r3,addr) \
  asm volatile("ldmatrix.sync.aligned.m8n8.x4.shared.b16 {%0,%1,%2,%3}, [%4];" \
    : "=r"(r0),"=r"(r1),"=r"(r2),"=r"(r3) : "r"(addr))
#define LDSM2T(r0,r1,addr) \
  asm volatile("ldmatrix.sync.aligned.m8n8.x2.trans.shared.b16 {%0,%1}, [%2];" \
    : "=r"(r0),"=r"(r1) : "r"(addr))
#define MMABF16(c,a,b0,b1) \
  asm volatile("mma.sync.aligned.m16n8k16.row.col.f32.bf16.bf16.f32 " \
    "{%0,%1,%2,%3}, {%4,%5,%6,%7}, {%8,%9}, {%0,%1,%2,%3};" \
    : "+f"((c)[0]),"+f"((c)[1]),"+f"((c)[2]),"+f"((c)[3]) \
    : "r"((a)[0]),"r"((a)[1]),"r"((a)[2]),"r"((a)[3]),"r"(b0),"r"(b1))

__device__ __forceinline__ uint32_t smem_u32(const void* p) {
    uint32_t a;
    asm("{ .reg .u64 t; cvta.to.shared.u64 t, %1; cvt.u32.u64 %0, t; }" : "=r"(a) : "l"(p));
    return a;
}

// ---------------- device scratch ----------------
__device__ float g_xs[(size_t)BB*TT*C2P*FF];        // features [B][T][C][F]
__device__ float g_mean[BB*FF*8];
__device__ float g_inv[BB*FF];
__device__ __nv_bfloat16 g_wa_hi[128*WSP];          // W hi/lo, [d][k], zero-padded
__device__ __nv_bfloat16 g_wa_lo[128*WSP];

// ---------------- K0: weight split ----------------
__global__ void wsplit_kernel(const float* __restrict__ conv_w) {
    for (int i = threadIdx.x; i < 128*WSP; i += blockDim.x) {
        int d = i / WSP, j = i - d*WSP;
        float v = (j < 100) ? conv_w[d*100 + j] : 0.f;
        __nv_bfloat16 h = __float2bfloat16(v);
        __nv_bfloat16 l = __float2bfloat16(v - __bfloat162float(h));
        g_wa_hi[i] = h;
        g_wa_lo[i] = l;
    }
}

// ---------------- K1: time stats ----------------
__global__ void stats_kernel(const float* __restrict__ x) {
    int b = blockIdx.x;
    int f = blockIdx.y;
    int tid = threadIdx.x;
    int ch = tid & 7;
    int tl = tid >> 3;

    float s = 0.f, q = 0.f;
    const float* px = x + ((size_t)b * TT * FF + f) * 8 + ch;
    #pragma unroll 4
    for (int t = tl; t < TT; t += 32) {
        float v = px[(size_t)t * FF * 8];
        s += v; q += v * v;
    }
    s += __shfl_xor_sync(0xffffffffu, s, 8);
    q += __shfl_xor_sync(0xffffffffu, q, 8);
    s += __shfl_xor_sync(0xffffffffu, s, 16);
    q += __shfl_xor_sync(0xffffffffu, q, 16);

    __shared__ float sb[8][8], qb[8][8];
    int warp = tid >> 5, lane = tid & 31;
    if (lane < 8) { sb[warp][lane] = s; qb[warp][lane] = q; }
    __syncthreads();

    if (tid == 0) {
        const float invT = 1.0f / (float)TT;
        float ssum[8], qsum[8];
        #pragma unroll
        for (int c = 0; c < 8; c++) {
            float a = 0.f, bq = 0.f;
            #pragma unroll
            for (int w = 0; w < 8; w++) { a += sb[w][c]; bq += qb[w][c]; }
            ssum[c] = a * invT; qsum[c] = bq * invT;
        }
        float tot = 0.f;
        #pragma unroll
        for (int m = 0; m < 4; m++) {
            float mr = ssum[m], mi = ssum[m + 4];
            tot += qsum[m] + qsum[m + 4] - mr * mr - mi * mi;
        }
        #pragma unroll
        for (int j = 0; j < 8; j++) g_mean[(b * FF + f) * 8 + j] = ssum[j];
        g_inv[b * FF + f] = rsqrtf(fmaxf(tot, 1e-10f));
    }
}

// ---------------- K2: SCM pair features ----------------
__global__ void feat_kernel(const float* __restrict__ x,
                            const float* __restrict__ expo,
                            const float* __restrict__ ipd) {
    int bt = blockIdx.x;
    int b  = bt / TT;

    for (int f = threadIdx.x; f < FF; f += blockDim.x) {
        const float* px = x + ((size_t)bt * FF + f) * 8;
        const float* mn = g_mean + (b * FF + f) * 8;
        float inv = g_inv[b * FF + f];

        float vr[4], vi[4];
        #pragma unroll
        for (int m = 0; m < 4; m++) {
            vr[m] = (px[m]     - mn[m])     * inv;
            vi[m] = (px[m + 4] - mn[m + 4]) * inv;
        }
        float s1 = 1.0f / (1.0f + expf(-expo[f]));
        float s2 = 1.0f / (1.0f + expf(-ipd[f]));

        const int ia[10] = {0,0,0,0,1,1,1,2,2,3};
        const int ja[10] = {0,1,2,3,1,2,3,2,3,3};
        float* ob = g_xs + (size_t)bt * C2P * FF + f;

        #pragma unroll
        for (int p = 0; p < 10; p++) {
            float re = vr[ia[p]] * vr[ja[p]] + vi[ia[p]] * vi[ja[p]];
            float im = vi[ia[p]] * vr[ja[p]] - vr[ia[p]] * vi[ja[p]];
            float a  = sqrtf(re * re + im * im);
            float beta = (a > 0.f) ? exp2f(s1 * log2f(a)) : 0.f;
            float mag  = a / (beta + 1e-10f);
            float ang  = atan2f(im, re) * s2;
            float sn, cs;
            sincosf(ang, &sn, &cs);
            ob[(size_t)(2 * p)     * FF] = mag * cs;
            ob[(size_t)(2 * p + 1) * FF] = mag * sn;
        }
    }
}

// ---------------- K3: HMMA bf16-split conv + LayerNorm ----------------
// 24 warps = 8 m-groups (16 d rows) x 3 n-groups (11 n-tiles of 8 f).
// Y = Whi*Xhi + Whi*Xlo + Wlo*Xhi (fp32 accum), D in registers, LN fused.
extern __shared__ char sm[];

__global__ void __launch_bounds__(NTH, 1)
conv_ln_kernel(const float* __restrict__ conv_b,
               const float* __restrict__ ln_w,
               const float* __restrict__ ln_b,
               float* __restrict__ out) {
    int bt = blockIdx.x;
    int b  = bt / TT;
    int t  = bt % TT;
    int tid = threadIdx.x;
    int warp = tid >> 5, lane = tid & 31;
    int g = lane >> 2, tg = lane & 3;
    int mg = warp & 7;          // d rows [16mg, 16mg+16)
    int ng = warp >> 3;         // f cols [88ng, 88ng+88)

    // ---- stage A (copy prebuilt hi/lo, coalesced u32) ----
    {
        const uint32_t* sh = (const uint32_t*)g_wa_hi;
        const uint32_t* sl = (const uint32_t*)g_wa_lo;
        uint32_t* dh = (uint32_t*)(sm + WS_HI);
        uint32_t* dl = (uint32_t*)(sm + WS_LO);
        for (int i = tid; i < 128*WSP/2; i += NTH) { dh[i] = sh[i]; dl[i] = sl[i]; }
    }

    // ---- stage B k-major [k][f]: warp per k-row, lane packs 2 f values ----
    for (int j = warp; j < KP; j += 24) {
        int c = j / 5, k = j - c * 5;
        int tt = t + k - 2;
        bool jv = (j < 100) && (tt >= 0) && (tt < TT);
        const float* src = jv ? (g_xs + ((size_t)(b*TT + tt)*C2P + c)*FF) : (const float*)0;
        uint32_t* rh = (uint32_t*)(sm + BS_HI) + j * (BSP/2);
        uint32_t* rl = (uint32_t*)(sm + BS_LO) + j * (BSP/2);
        for (int fp = lane; fp < NFP/2; fp += 32) {
            int f0 = 2*fp;
            float v0 = (jv && f0     < FF) ? src[f0]     : 0.f;
            float v1 = (jv && f0 + 1 < FF) ? src[f0 + 1] : 0.f;
            __nv_bfloat16 h0 = __float2bfloat16(v0);
            __nv_bfloat16 h1 = __float2bfloat16(v1);
            __nv_bfloat16 l0 = __float2bfloat16(v0 - __bfloat162float(h0));
            __nv_bfloat16 l1 = __float2bfloat16(v1 - __bfloat162float(h1));
            rh[fp] = (uint32_t)__bfloat16_as_ushort(h0) | ((uint32_t)__bfloat16_as_ushort(h1) << 16);
            rl[fp] = (uint32_t)__bfloat16_as_ushort(l0) | ((uint32_t)__bfloat16_as_ushort(l1) << 16);
        }
    }
    __syncthreads();

    // ---- mainloop ----
    float acc[11][4];
    #pragma unroll
    for (int nt = 0; nt < 11; nt++)
        #pragma unroll
        for (int ci = 0; ci < 4; ci++) acc[nt][ci] = 0.f;

    uint32_t sb = smem_u32(sm);
    int aRow = (lane & 7) + 8 * ((lane >> 3) & 1);
    int aK   = (lane >> 4) * 8;
    uint32_t aoff = sb + WS_HI + (uint32_t)(((16*mg + aRow) * WSP + aK) * 2);
    uint32_t boff = sb + BS_HI + (uint32_t)((aRow * BSP + 88*ng) * 2);

    for (int kt = 0; kt < 7; kt++) {
        uint32_t ah[4], al[4];
        uint32_t a = aoff + kt * 32;
        LDSM4(ah[0], ah[1], ah[2], ah[3], a);
        LDSM4(al[0], al[1], al[2], al[3], a + (WS_LO - WS_HI));
        #pragma unroll
        for (int nt = 0; nt < 11; nt++) {
            uint32_t badr = boff + kt * (16*BSP*2) + nt * 16;
            uint32_t bh0, bh1, bl0, bl1;
            LDSM2T(bh0, bh1, badr);
            LDSM2T(bl0, bl1, badr + (BS_LO - BS_HI));
            MMABF16(acc[nt], ah, bh0, bh1);
            MMABF16(acc[nt], ah, bl0, bl1);
            MMABF16(acc[nt], al, bh0, bh1);
        }
    }

    // ---- bias ----
    float bias0 = conv_b[16*mg + g];
    float bias1 = conv_b[16*mg + 8 + g];

    // ---- LN stats from registers ----
    float* red = (float*)(sm + SRED);
    float s = 0.f, q = 0.f;
    #pragma unroll
    for (int nt = 0; nt < 11; nt++) {
        int fb = 88*ng + 8*nt + 2*tg;
        if (fb < FF) {
            float v0 = acc[nt][0] + bias0;
            float v2 = acc[nt][2] + bias1;
            s += v0 + v2; q += v0*v0 + v2*v2;
        }
        if (fb + 1 < FF) {
            float v1 = acc[nt][1] + bias0;
            float v3 = acc[nt][3] + bias1;
            s += v1 + v3; q += v1*v1 + v3*v3;
        }
    }
    #pragma unroll
    for (int o = 16; o > 0; o >>= 1) {
        s += __shfl_xor_sync(0xffffffffu, s, o);
        q += __shfl_xor_sync(0xffffffffu, q, o);
    }
    if (lane == 0) { red[warp] = s; red[24 + warp] = q; }
    __syncthreads();
    if (tid < 32) {
        s = (tid < 24) ? red[tid] : 0.f;
        q = (tid < 24) ? red[24 + tid] : 0.f;
        #pragma unroll
        for (int o = 16; o > 0; o >>= 1) {
            s += __shfl_xor_sync(0xffffffffu, s, o);
            q += __shfl_xor_sync(0xffffffffu, q, o);
        }
        if (tid == 0) {
            const float invN = 1.0f / (float)NLN;
            float mu  = s * invN;
            float var = q * invN - mu * mu;
            red[48] = mu;
            red[49] = rsqrtf(var + 1e-5f);
        }
    }
    __syncthreads();
    float mu = red[48], rs = red[49];

    // ---- normalize + store ----
    float* po = out + (size_t)bt * NLN;
    int r0 = (16*mg + g) * FF;
    int r1 = r0 + 8 * FF;
    #pragma unroll
    for (int nt = 0; nt < 11; nt++) {
        int fb = 88*ng + 8*nt + 2*tg;
        if (fb < FF) {
            int o0 = r0 + fb, o1 = r1 + fb;
            po[o0] = (acc[nt][0] + bias0 - mu) * rs * ln_w[o0] + ln_b[o0];
            po[o1] = (acc[nt][2] + bias1 - mu) * rs * ln_w[o1] + ln_b[o1];
        }
        if (fb + 1 < FF) {
            int o0 = r0 + fb + 1, o1 = r1 + fb + 1;
            po[o0] = (acc[nt][1] + bias0 - mu) * rs * ln_w[o0] + ln_b[o0];
            po[o1] = (acc[nt][3] + bias1 - mu) * rs * ln_w[o1] + ln_b[o1];
        }
    }
}

// ---------------- launch ----------------
extern "C" void kernel_launch(void* const* d_in, const int* in_sizes, int n_in,
                              void* d_out, int out_size) {
    const float* x    = (const float*)d_in[0];
    const float* expo = (const float*)d_in[1];
    const float* ipd  = (const float*)d_in[2];
    const float* cw   = (const float*)d_in[3];
    const float* cb   = (const float*)d_in[4];
    const float* lw   = (const float*)d_in[5];
    const float* lb   = (const float*)d_in[6];
    float* out = (float*)d_out;

    wsplit_kernel<<<1, 256>>>(cw);
    stats_kernel<<<dim3(BB, FF), 256>>>(x);
    feat_kernel<<<BB * TT, 256>>>(x, expo, ipd);

    cudaFuncSetAttribute(conv_ln_kernel,
                         cudaFuncAttributeMaxDynamicSharedMemorySize, SM_TOTAL);
    conv_ln_kernel<<<BB * TT, NTH, SM_TOTAL>>>(cb, lw, lb, out);
}

// round 12
// speedup vs baseline: 1.3495x; 1.1653x over previous
#include <cuda_runtime.h>
#include <cuda_bf16.h>
#include <math.h>
#include <stdint.h>

#define BB 4
#define TT 512
#define FF 257
#define DD 128
#define C2P 20
#define NLN (DD*FF)
#define NTH 768

#define KP   112
#define WSP  120           // A pitch (bf16)
#define BSP  264           // B pitch (bf16)
#define NFP  264           // padded f (33 n-tiles of 8)

// smem byte offsets
#define WS_HI 0
#define WS_LO (WS_HI + 128*WSP*2)      // 30720
#define BS_HI (WS_LO + 128*WSP*2)      // 61440
#define BS_LO (BS_HI + KP*BSP*2)       // 120576  (B region ends 179712)
#define SLNWB BS_HI                    // lnwb reuses B region: 131584 B -> ends 193024
#define SRED  (BS_HI + NLN*4)          // 193024
#define SM_TOTAL (SRED + 224)          // 193248

#define LDSM4(r0,r1,r2,r3,addr) \
  asm volatile("ldmatrix.sync.aligned.m8n8.x4.shared.b16 {%0,%1,%2,%3}, [%4];" \
    : "=r"(r0),"=r"(r1),"=r"(r2),"=r"(r3) : "r"(addr))
#define LDSM2T(r0,r1,addr) \
  asm volatile("ldmatrix.sync.aligned.m8n8.x2.trans.shared.b16 {%0,%1}, [%2];" \
    : "=r"(r0),"=r"(r1) : "r"(addr))
#define MMABF16(c,a,b0,b1) \
  asm volatile("mma.sync.aligned.m16n8k16.row.col.f32.bf16.bf16.f32 " \
    "{%0,%1,%2,%3}, {%4,%5,%6,%7}, {%8,%9}, {%0,%1,%2,%3};" \
    : "+f"((c)[0]),"+f"((c)[1]),"+f"((c)[2]),"+f"((c)[3]) \
    : "r"((a)[0]),"r"((a)[1]),"r"((a)[2]),"r"((a)[3]),"r"(b0),"r"(b1))

__device__ __forceinline__ uint32_t smem_u32(const void* p) {
    uint32_t a;
    asm("{ .reg .u64 t; cvta.to.shared.u64 t, %1; cvt.u32.u64 %0, t; }" : "=r"(a) : "l"(p));
    return a;
}
__device__ __forceinline__ float bf16lo(uint32_t u) {
    return __bfloat162float(__ushort_as_bfloat16((unsigned short)(u & 0xffffu)));
}
__device__ __forceinline__ float bf16hi(uint32_t u) {
    return __bfloat162float(__ushort_as_bfloat16((unsigned short)(u >> 16)));
}

// ---------------- device scratch ----------------
__device__ float g_xs[(size_t)BB*TT*C2P*FF];
__device__ float g_mean[BB*FF*8];
__device__ float g_inv[BB*FF];
__device__ __nv_bfloat16 g_wa_hi[128*WSP];
__device__ __nv_bfloat16 g_wa_lo[128*WSP];
__device__ uint32_t g_lnwb[NLN];       // packed (ln_w bf16 | ln_b bf16 << 16)

// ---------------- K0a: weight split ----------------
__global__ void wsplit_kernel(const float* __restrict__ conv_w) {
    for (int i = threadIdx.x; i < 128*WSP; i += blockDim.x) {
        int d = i / WSP, j = i - d*WSP;
        float v = (j < 100) ? conv_w[d*100 + j] : 0.f;
        __nv_bfloat16 h = __float2bfloat16(v);
        __nv_bfloat16 l = __float2bfloat16(v - __bfloat162float(h));
        g_wa_hi[i] = h;
        g_wa_lo[i] = l;
    }
}

// ---------------- K0b: ln param pack ----------------
__global__ void lnpack_kernel(const float* __restrict__ lw,
                              const float* __restrict__ lb) {
    int i = blockIdx.x * blockDim.x + threadIdx.x;
    if (i < NLN) {
        unsigned short w = __bfloat16_as_ushort(__float2bfloat16(lw[i]));
        unsigned short b = __bfloat16_as_ushort(__float2bfloat16(lb[i]));
        g_lnwb[i] = (uint32_t)w | ((uint32_t)b << 16);
    }
}

// ---------------- K1: time stats ----------------
__global__ void stats_kernel(const float* __restrict__ x) {
    int b = blockIdx.x;
    int f = blockIdx.y;
    int tid = threadIdx.x;
    int ch = tid & 7;
    int tl = tid >> 3;

    float s = 0.f, q = 0.f;
    const float* px = x + ((size_t)b * TT * FF + f) * 8 + ch;
    #pragma unroll 4
    for (int t = tl; t < TT; t += 32) {
        float v = px[(size_t)t * FF * 8];
        s += v; q += v * v;
    }
    s += __shfl_xor_sync(0xffffffffu, s, 8);
    q += __shfl_xor_sync(0xffffffffu, q, 8);
    s += __shfl_xor_sync(0xffffffffu, s, 16);
    q += __shfl_xor_sync(0xffffffffu, q, 16);

    __shared__ float sb[8][8], qb[8][8];
    int warp = tid >> 5, lane = tid & 31;
    if (lane < 8) { sb[warp][lane] = s; qb[warp][lane] = q; }
    __syncthreads();

    if (tid == 0) {
        const float invT = 1.0f / (float)TT;
        float ssum[8], qsum[8];
        #pragma unroll
        for (int c = 0; c < 8; c++) {
            float a = 0.f, bq = 0.f;
            #pragma unroll
            for (int w = 0; w < 8; w++) { a += sb[w][c]; bq += qb[w][c]; }
            ssum[c] = a * invT; qsum[c] = bq * invT;
        }
        float tot = 0.f;
        #pragma unroll
        for (int m = 0; m < 4; m++) {
            float mr = ssum[m], mi = ssum[m + 4];
            tot += qsum[m] + qsum[m + 4] - mr * mr - mi * mi;
        }
        #pragma unroll
        for (int j = 0; j < 8; j++) g_mean[(b * FF + f) * 8 + j] = ssum[j];
        g_inv[b * FF + f] = rsqrtf(fmaxf(tot, 1e-10f));
    }
}

// ---------------- K2: SCM pair features ----------------
__global__ void feat_kernel(const float* __restrict__ x,
                            const float* __restrict__ expo,
                            const float* __restrict__ ipd) {
    int bt = blockIdx.x;
    int b  = bt / TT;

    for (int f = threadIdx.x; f < FF; f += blockDim.x) {
        const float* px = x + ((size_t)bt * FF + f) * 8;
        const float* mn = g_mean + (b * FF + f) * 8;
        float inv = g_inv[b * FF + f];

        float vr[4], vi[4];
        #pragma unroll
        for (int m = 0; m < 4; m++) {
            vr[m] = (px[m]     - mn[m])     * inv;
            vi[m] = (px[m + 4] - mn[m + 4]) * inv;
        }
        float s1 = 1.0f / (1.0f + expf(-expo[f]));
        float s2 = 1.0f / (1.0f + expf(-ipd[f]));

        const int ia[10] = {0,0,0,0,1,1,1,2,2,3};
        const int ja[10] = {0,1,2,3,1,2,3,2,3,3};
        float* ob = g_xs + (size_t)bt * C2P * FF + f;

        #pragma unroll
        for (int p = 0; p < 10; p++) {
            float re = vr[ia[p]] * vr[ja[p]] + vi[ia[p]] * vi[ja[p]];
            float im = vi[ia[p]] * vr[ja[p]] - vr[ia[p]] * vi[ja[p]];
            float a  = sqrtf(re * re + im * im);
            float beta = (a > 0.f) ? exp2f(s1 * log2f(a)) : 0.f;
            float mag  = a / (beta + 1e-10f);
            float ang  = atan2f(im, re) * s2;
            float sn, cs;
            sincosf(ang, &sn, &cs);
            ob[(size_t)(2 * p)     * FF] = mag * cs;
            ob[(size_t)(2 * p + 1) * FF] = mag * sn;
        }
    }
}

// ---------------- K3: HMMA bf16-split conv + LayerNorm ----------------
extern __shared__ char sm[];

__global__ void __launch_bounds__(NTH, 1)
conv_ln_kernel(const float* __restrict__ conv_b,
               float* __restrict__ out) {
    int bt = blockIdx.x;
    int b  = bt / TT;
    int t  = bt % TT;
    int tid = threadIdx.x;
    int warp = tid >> 5, lane = tid & 31;
    int g = lane >> 2, tg = lane & 3;
    int mg = warp & 7;          // d rows [16mg, 16mg+16)
    int ng = warp >> 3;         // f cols [88ng, 88ng+88)

    // ---- stage A ----
    {
        const uint32_t* sh = (const uint32_t*)g_wa_hi;
        const uint32_t* sl = (const uint32_t*)g_wa_lo;
        uint32_t* dh = (uint32_t*)(sm + WS_HI);
        uint32_t* dl = (uint32_t*)(sm + WS_LO);
        for (int i = tid; i < 128*WSP/2; i += NTH) { dh[i] = sh[i]; dl[i] = sl[i]; }
    }

    // ---- stage B k-major [k][f] ----
    for (int j = warp; j < KP; j += 24) {
        int c = j / 5, k = j - c * 5;
        int tt = t + k - 2;
        bool jv = (j < 100) && (tt >= 0) && (tt < TT);
        const float* src = jv ? (g_xs + ((size_t)(b*TT + tt)*C2P + c)*FF) : (const float*)0;
        uint32_t* rh = (uint32_t*)(sm + BS_HI) + j * (BSP/2);
        uint32_t* rl = (uint32_t*)(sm + BS_LO) + j * (BSP/2);
        for (int fp = lane; fp < NFP/2; fp += 32) {
            int f0 = 2*fp;
            float v0 = (jv && f0     < FF) ? src[f0]     : 0.f;
            float v1 = (jv && f0 + 1 < FF) ? src[f0 + 1] : 0.f;
            __nv_bfloat16 h0 = __float2bfloat16(v0);
            __nv_bfloat16 h1 = __float2bfloat16(v1);
            __nv_bfloat16 l0 = __float2bfloat16(v0 - __bfloat162float(h0));
            __nv_bfloat16 l1 = __float2bfloat16(v1 - __bfloat162float(h1));
            rh[fp] = (uint32_t)__bfloat16_as_ushort(h0) | ((uint32_t)__bfloat16_as_ushort(h1) << 16);
            rl[fp] = (uint32_t)__bfloat16_as_ushort(l0) | ((uint32_t)__bfloat16_as_ushort(l1) << 16);
        }
    }
    __syncthreads();

    // ---- mainloop ----
    float acc[11][4];
    #pragma unroll
    for (int nt = 0; nt < 11; nt++)
        #pragma unroll
        for (int ci = 0; ci < 4; ci++) acc[nt][ci] = 0.f;

    uint32_t sb = smem_u32(sm);
    int aRow = (lane & 7) + 8 * ((lane >> 3) & 1);
    int aK   = (lane >> 4) * 8;
    uint32_t aoff = sb + WS_HI + (uint32_t)(((16*mg + aRow) * WSP + aK) * 2);
    uint32_t boff = sb + BS_HI + (uint32_t)((aRow * BSP + 88*ng) * 2);

    for (int kt = 0; kt < 7; kt++) {
        uint32_t ah[4], al[4];
        uint32_t a = aoff + kt * 32;
        LDSM4(ah[0], ah[1], ah[2], ah[3], a);
        LDSM4(al[0], al[1], al[2], al[3], a + (WS_LO - WS_HI));
        #pragma unroll
        for (int nt = 0; nt < 11; nt++) {
            uint32_t badr = boff + kt * (16*BSP*2) + nt * 16;
            uint32_t bh0, bh1, bl0, bl1;
            LDSM2T(bh0, bh1, badr);
            LDSM2T(bl0, bl1, badr + (BS_LO - BS_HI));
            MMABF16(acc[nt], ah, bh0, bh1);
            MMABF16(acc[nt], ah, bl0, bl1);
            MMABF16(acc[nt], al, bh0, bh1);
        }
    }
    __syncthreads();   // B region dead; safe to overwrite with lnwb

    // ---- start lnwb copy into smem (overlaps stats reduction) ----
    {
        uint32_t* dst = (uint32_t*)(sm + SLNWB);
        for (int i = tid; i < NLN; i += NTH) dst[i] = g_lnwb[i];
    }

    // ---- bias ----
    float bias0 = conv_b[16*mg + g];
    float bias1 = conv_b[16*mg + 8 + g];

    // ---- LN stats from registers ----
    float* red = (float*)(sm + SRED);
    float s = 0.f, q = 0.f;
    if (ng < 2) {
        #pragma unroll
        for (int nt = 0; nt < 11; nt++) {
            float v0 = acc[nt][0] + bias0;
            float v1 = acc[nt][1] + bias0;
            float v2 = acc[nt][2] + bias1;
            float v3 = acc[nt][3] + bias1;
            s += (v0 + v1) + (v2 + v3);
            q += (v0*v0 + v1*v1) + (v2*v2 + v3*v3);
        }
    } else {
        #pragma unroll
        for (int nt = 0; nt < 11; nt++) {
            int fb = 176 + 8*nt + 2*tg;
            if (fb < FF) {
                float v0 = acc[nt][0] + bias0;
                float v2 = acc[nt][2] + bias1;
                s += v0 + v2; q += v0*v0 + v2*v2;
            }
            if (fb + 1 < FF) {
                float v1 = acc[nt][1] + bias0;
                float v3 = acc[nt][3] + bias1;
                s += v1 + v3; q += v1*v1 + v3*v3;
            }
        }
    }
    #pragma unroll
    for (int o = 16; o > 0; o >>= 1) {
        s += __shfl_xor_sync(0xffffffffu, s, o);
        q += __shfl_xor_sync(0xffffffffu, q, o);
    }
    if (lane == 0) { red[warp] = s; red[24 + warp] = q; }
    __syncthreads();
    if (tid < 32) {
        s = (tid < 24) ? red[tid] : 0.f;
        q = (tid < 24) ? red[24 + tid] : 0.f;
        #pragma unroll
        for (int o = 16; o > 0; o >>= 1) {
            s += __shfl_xor_sync(0xffffffffu, s, o);
            q += __shfl_xor_sync(0xffffffffu, q, o);
        }
        if (tid == 0) {
            const float invN = 1.0f / (float)NLN;
            float mu  = s * invN;
            float var = q * invN - mu * mu;
            red[48] = mu;
            red[49] = rsqrtf(var + 1e-5f);
        }
    }
    __syncthreads();
    float mu = red[48], rs = red[49];

    // ---- normalize + store (ln params from smem) ----
    const uint32_t* lnwb = (const uint32_t*)(sm + SLNWB);
    float* po = out + (size_t)bt * NLN;
    int r0 = (16*mg + g) * FF;
    int r1 = r0 + 8 * FF;
    if (ng < 2) {
        #pragma unroll
        for (int nt = 0; nt < 11; nt++) {
            int fb = 88*ng + 8*nt + 2*tg;
            int o0 = r0 + fb, o1 = r1 + fb;
            uint32_t w00 = lnwb[o0],     w01 = lnwb[o0 + 1];
            uint32_t w10 = lnwb[o1],     w11 = lnwb[o1 + 1];
            po[o0]     = (acc[nt][0] + bias0 - mu) * rs * bf16lo(w00) + bf16hi(w00);
            po[o0 + 1] = (acc[nt][1] + bias0 - mu) * rs * bf16lo(w01) + bf16hi(w01);
            po[o1]     = (acc[nt][2] + bias1 - mu) * rs * bf16lo(w10) + bf16hi(w10);
            po[o1 + 1] = (acc[nt][3] + bias1 - mu) * rs * bf16lo(w11) + bf16hi(w11);
        }
    } else {
        #pragma unroll
        for (int nt = 0; nt < 11; nt++) {
            int fb = 176 + 8*nt + 2*tg;
            if (fb < FF) {
                int o0 = r0 + fb, o1 = r1 + fb;
                uint32_t w00 = lnwb[o0], w10 = lnwb[o1];
                po[o0] = (acc[nt][0] + bias0 - mu) * rs * bf16lo(w00) + bf16hi(w00);
                po[o1] = (acc[nt][2] + bias1 - mu) * rs * bf16lo(w10) + bf16hi(w10);
            }
            if (fb + 1 < FF) {
                int o0 = r0 + fb + 1, o1 = r1 + fb + 1;
                uint32_t w01 = lnwb[o0], w11 = lnwb[o1];
                po[o0] = (acc[nt][1] + bias0 - mu) * rs * bf16lo(w01) + bf16hi(w01);
                po[o1] = (acc[nt][3] + bias1 - mu) * rs * bf16lo(w11) + bf16hi(w11);
            }
        }
    }
}

// ---------------- launch ----------------
extern "C" void kernel_launch(void* const* d_in, const int* in_sizes, int n_in,
                              void* d_out, int out_size) {
    const float* x    = (const float*)d_in[0];
    const float* expo = (const float*)d_in[1];
    const float* ipd  = (const float*)d_in[2];
    const float* cw   = (const float*)d_in[3];
    const float* cb   = (const float*)d_in[4];
    const float* lw   = (const float*)d_in[5];
    const float* lb   = (const float*)d_in[6];
    float* out = (float*)d_out;

    wsplit_kernel<<<1, 256>>>(cw);
    lnpack_kernel<<<(NLN + 511) / 512, 512>>>(lw, lb);
    stats_kernel<<<dim3(BB, FF), 256>>>(x);
    feat_kernel<<<BB * TT, 256>>>(x, expo, ipd);

    cudaFuncSetAttribute(conv_ln_kernel,
                         cudaFuncAttributeMaxDynamicSharedMemorySize, SM_TOTAL);
    conv_ln_kernel<<<BB * TT, NTH, SM_TOTAL>>>(cb, out);
}

// round 13
// speedup vs baseline: 1.7555x; 1.3008x over previous
#include <cuda_runtime.h>
#include <cuda_bf16.h>
#include <math.h>
#include <stdint.h>

#define BB 4
#define TT 512
#define FF 257
#define DD 128
#define C2P 20
#define NLN (DD*FF)
#define NTH 768

#define KP   112
#define WSP  120           // A pitch (bf16): 240B rows
#define BSP  264           // B pitch (elements): 528B rows (33x16B)
#define XSP  264           // g_xh/g_xl row pitch (elements)

// smem byte offsets
#define WS_HI 0
#define WS_LO (WS_HI + 128*WSP*2)      // 30720
#define BS_HI (WS_LO + 128*WSP*2)      // 61440
#define BS_LO (BS_HI + KP*BSP*2)       // 120576
#define SLNWB BS_HI                    // lnwb reuses B region after mainloop
#define SRED  (BS_HI + NLN*4)          // 193024
#define SM_TOTAL (SRED + 224)

#define LDSM4(r0,r1,r2,r3,addr) \
  asm volatile("ldmatrix.sync.aligned.m8n8.x4.shared.b16 {%0,%1,%2,%3}, [%4];" \
    : "=r"(r0),"=r"(r1),"=r"(r2),"=r"(r3) : "r"(addr))
#define LDSM2T(r0,r1,addr) \
  asm volatile("ldmatrix.sync.aligned.m8n8.x2.trans.shared.b16 {%0,%1}, [%2];" \
    : "=r"(r0),"=r"(r1) : "r"(addr))
#define MMABF16(c,a,b0,b1) \
  asm volatile("mma.sync.aligned.m16n8k16.row.col.f32.bf16.bf16.f32 " \
    "{%0,%1,%2,%3}, {%4,%5,%6,%7}, {%8,%9}, {%0,%1,%2,%3};" \
    : "+f"((c)[0]),"+f"((c)[1]),"+f"((c)[2]),"+f"((c)[3]) \
    : "r"((a)[0]),"r"((a)[1]),"r"((a)[2]),"r"((a)[3]),"r"(b0),"r"(b1))

#define CP16(d,s)    asm volatile("cp.async.cg.shared.global [%0], [%1], 16;" :: "r"(d), "l"(s) : "memory")
#define CP16Z(d,s,z) asm volatile("cp.async.cg.shared.global [%0], [%1], 16, %2;" :: "r"(d), "l"(s), "r"(z) : "memory")
#define CPCOMMIT()   asm volatile("cp.async.commit_group;" ::: "memory")
#define CPWAITALL()  asm volatile("cp.async.wait_group 0;" ::: "memory")

__device__ __forceinline__ uint32_t smem_u32(const void* p) {
    uint32_t a;
    asm("{ .reg .u64 t; cvta.to.shared.u64 t, %1; cvt.u32.u64 %0, t; }" : "=r"(a) : "l"(p));
    return a;
}
__device__ __forceinline__ float bf16lo(uint32_t u) {
    return __bfloat162float(__ushort_as_bfloat16((unsigned short)(u & 0xffffu)));
}
__device__ __forceinline__ float bf16hi(uint32_t u) {
    return __bfloat162float(__ushort_as_bfloat16((unsigned short)(u >> 16)));
}

// ---------------- device scratch ----------------
__device__ float g_mean[BB*FF*8];
__device__ float g_inv[BB*FF];
__device__ float g_s1[FF];
__device__ float g_s2[FF];
__device__ __align__(16) __nv_bfloat16 g_wa_hi[128*WSP];
__device__ __align__(16) __nv_bfloat16 g_wa_lo[128*WSP];
__device__ __align__(16) uint32_t g_lnwb[NLN];
// features as bf16 hi/lo, rows [(b*TT+t)*C2P + c] of XSP elts (zero-init pads)
__device__ __align__(16) __nv_bfloat16 g_xh[(size_t)BB*TT*C2P*XSP];
__device__ __align__(16) __nv_bfloat16 g_xl[(size_t)BB*TT*C2P*XSP];

// ---------------- K0a: weight split ----------------
__global__ void wsplit_kernel(const float* __restrict__ conv_w) {
    for (int i = threadIdx.x; i < 128*WSP; i += blockDim.x) {
        int d = i / WSP, j = i - d*WSP;
        float v = (j < 100) ? conv_w[d*100 + j] : 0.f;
        __nv_bfloat16 h = __float2bfloat16(v);
        __nv_bfloat16 l = __float2bfloat16(v - __bfloat162float(h));
        g_wa_hi[i] = h;
        g_wa_lo[i] = l;
    }
}

// ---------------- K0b: ln param pack + sigmoids ----------------
__global__ void lnpack_kernel(const float* __restrict__ lw,
                              const float* __restrict__ lb,
                              const float* __restrict__ expo,
                              const float* __restrict__ ipd) {
    int i = blockIdx.x * blockDim.x + threadIdx.x;
    if (i < NLN) {
        unsigned short w = __bfloat16_as_ushort(__float2bfloat16(lw[i]));
        unsigned short b = __bfloat16_as_ushort(__float2bfloat16(lb[i]));
        g_lnwb[i] = (uint32_t)w | ((uint32_t)b << 16);
    }
    if (i < FF) {
        g_s1[i] = 1.0f / (1.0f + expf(-expo[i]));
        g_s2[i] = 1.0f / (1.0f + expf(-ipd[i]));
    }
}

// ---------------- K1: time stats ----------------
__global__ void stats_kernel(const float* __restrict__ x) {
    int b = blockIdx.x;
    int f = blockIdx.y;
    int tid = threadIdx.x;
    int ch = tid & 7;
    int tl = tid >> 3;

    float s = 0.f, q = 0.f;
    const float* px = x + ((size_t)b * TT * FF + f) * 8 + ch;
    #pragma unroll 4
    for (int t = tl; t < TT; t += 32) {
        float v = px[(size_t)t * FF * 8];
        s += v; q += v * v;
    }
    s += __shfl_xor_sync(0xffffffffu, s, 8);
    q += __shfl_xor_sync(0xffffffffu, q, 8);
    s += __shfl_xor_sync(0xffffffffu, s, 16);
    q += __shfl_xor_sync(0xffffffffu, q, 16);

    __shared__ float sb[8][8], qb[8][8];
    int warp = tid >> 5, lane = tid & 31;
    if (lane < 8) { sb[warp][lane] = s; qb[warp][lane] = q; }
    __syncthreads();

    if (tid == 0) {
        const float invT = 1.0f / (float)TT;
        float ssum[8], qsum[8];
        #pragma unroll
        for (int c = 0; c < 8; c++) {
            float a = 0.f, bq = 0.f;
            #pragma unroll
            for (int w = 0; w < 8; w++) { a += sb[w][c]; bq += qb[w][c]; }
            ssum[c] = a * invT; qsum[c] = bq * invT;
        }
        float tot = 0.f;
        #pragma unroll
        for (int m = 0; m < 4; m++) {
            float mr = ssum[m], mi = ssum[m + 4];
            tot += qsum[m] + qsum[m + 4] - mr * mr - mi * mi;
        }
        #pragma unroll
        for (int j = 0; j < 8; j++) g_mean[(b * FF + f) * 8 + j] = ssum[j];
        g_inv[b * FF + f] = rsqrtf(fmaxf(tot, 1e-10f));
    }
}

// ---------------- K2: SCM pair features -> bf16 hi/lo ----------------
// 512 threads: fi = tid&255 covers f (fi and fi+256), half = tid>>8 covers 5 pairs.
__global__ void feat_kernel(const float* __restrict__ x) {
    int bt = blockIdx.x;
    int b  = bt / TT;
    int tid = threadIdx.x;
    int fi = tid & 255, half = tid >> 8;

    const int ia[10] = {0,0,0,0,1,1,1,2,2,3};
    const int ja[10] = {0,1,2,3,1,2,3,2,3,3};

    for (int f = fi; f < FF; f += 256) {
        const float* px = x + ((size_t)bt * FF + f) * 8;
        const float* mn = g_mean + (b * FF + f) * 8;
        float inv = g_inv[b * FF + f];

        float vr[4], vi[4];
        #pragma unroll
        for (int m = 0; m < 4; m++) {
            vr[m] = (px[m]     - mn[m])     * inv;
            vi[m] = (px[m + 4] - mn[m + 4]) * inv;
        }
        float s1 = g_s1[f];
        float s2 = g_s2[f];

        size_t rowbase = (size_t)bt * C2P * XSP + f;
        #pragma unroll
        for (int pp = 0; pp < 5; pp++) {
            int p = 5 * half + pp;
            float re = vr[ia[p]] * vr[ja[p]] + vi[ia[p]] * vi[ja[p]];
            float im = vi[ia[p]] * vr[ja[p]] - vr[ia[p]] * vi[ja[p]];
            float a  = sqrtf(re * re + im * im);
            float beta = (a > 0.f) ? exp2f(s1 * log2f(a)) : 0.f;
            float mag  = a / (beta + 1e-10f);
            float ang  = atan2f(im, re) * s2;
            float sn, cs;
            sincosf(ang, &sn, &cs);
            float v0 = mag * cs, v1 = mag * sn;
            __nv_bfloat16 h0 = __float2bfloat16(v0);
            __nv_bfloat16 h1 = __float2bfloat16(v1);
            size_t r0 = rowbase + (size_t)(2 * p) * XSP;
            size_t r1 = r0 + XSP;
            g_xh[r0] = h0;
            g_xl[r0] = __float2bfloat16(v0 - __bfloat162float(h0));
            g_xh[r1] = h1;
            g_xl[r1] = __float2bfloat16(v1 - __bfloat162float(h1));
        }
    }
}

// ---------------- K3: HMMA bf16-split conv + LayerNorm ----------------
extern __shared__ char sm[];

__global__ void __launch_bounds__(NTH, 1)
conv_ln_kernel(const float* __restrict__ conv_b,
               float* __restrict__ out) {
    int bt = blockIdx.x;
    int b  = bt / TT;
    int t  = bt % TT;
    int tid = threadIdx.x;
    int warp = tid >> 5, lane = tid & 31;
    int g = lane >> 2, tg = lane & 3;
    int mg = warp & 7;          // d rows [16mg, 16mg+16)
    int ng = warp >> 3;         // f cols [88ng, 88ng+88)

    uint32_t sb = smem_u32(sm);

    // ---- stage A via cp.async (flat 16B chunks, both buffers) ----
    for (int i = tid * 16; i < 128*WSP*2; i += NTH * 16) {
        CP16(sb + WS_HI + i, (const char*)g_wa_hi + i);
        CP16(sb + WS_LO + i, (const char*)g_wa_lo + i);
    }

    // ---- stage B rows via cp.async (zero-fill invalid / pad rows) ----
    for (int j = warp; j < KP; j += 24) {
        int c = j / 5, k = j - c * 5;
        int tt = t + k - 2;
        bool jv = (j < 100) && (tt >= 0) && (tt < TT);
        size_t ro = jv ? ((size_t)((b*TT + tt)*C2P + c) * XSP) * 2 : 0;
        const char* sh = (const char*)g_xh + ro;
        const char* sl = (const char*)g_xl + ro;
        uint32_t dh = sb + BS_HI + j * (BSP*2);
        uint32_t dl = sb + BS_LO + j * (BSP*2);
        int sz = jv ? 16 : 0;
        for (int ch = lane * 16; ch < BSP*2; ch += 32 * 16) {
            CP16Z(dh + ch, sh + ch, sz);
            CP16Z(dl + ch, sl + ch, sz);
        }
    }
    CPCOMMIT();
    CPWAITALL();
    __syncthreads();

    // ---- mainloop (unchanged) ----
    float acc[11][4];
    #pragma unroll
    for (int nt = 0; nt < 11; nt++)
        #pragma unroll
        for (int ci = 0; ci < 4; ci++) acc[nt][ci] = 0.f;

    int aRow = (lane & 7) + 8 * ((lane >> 3) & 1);
    int aK   = (lane >> 4) * 8;
    uint32_t aoff = sb + WS_HI + (uint32_t)(((16*mg + aRow) * WSP + aK) * 2);
    uint32_t boff = sb + BS_HI + (uint32_t)((aRow * BSP + 88*ng) * 2);

    for (int kt = 0; kt < 7; kt++) {
        uint32_t ah[4], al[4];
        uint32_t a = aoff + kt * 32;
        LDSM4(ah[0], ah[1], ah[2], ah[3], a);
        LDSM4(al[0], al[1], al[2], al[3], a + (WS_LO - WS_HI));
        #pragma unroll
        for (int nt = 0; nt < 11; nt++) {
            uint32_t badr = boff + kt * (16*BSP*2) + nt * 16;
            uint32_t bh0, bh1, bl0, bl1;
            LDSM2T(bh0, bh1, badr);
            LDSM2T(bl0, bl1, badr + (BS_LO - BS_HI));
            MMABF16(acc[nt], ah, bh0, bh1);
            MMABF16(acc[nt], ah, bl0, bl1);
            MMABF16(acc[nt], al, bh0, bh1);
        }
    }
    __syncthreads();   // B region dead

    // ---- lnwb copy via cp.async (latency hides behind stats reduction) ----
    for (int i = tid * 16; i < NLN * 4; i += NTH * 16)
        CP16(sb + SLNWB + i, (const char*)g_lnwb + i);
    CPCOMMIT();

    // ---- bias ----
    float bias0 = conv_b[16*mg + g];
    float bias1 = conv_b[16*mg + 8 + g];

    // ---- LN stats from registers ----
    float* red = (float*)(sm + SRED);
    float s = 0.f, q = 0.f;
    if (ng < 2) {
        #pragma unroll
        for (int nt = 0; nt < 11; nt++) {
            float v0 = acc[nt][0] + bias0;
            float v1 = acc[nt][1] + bias0;
            float v2 = acc[nt][2] + bias1;
            float v3 = acc[nt][3] + bias1;
            s += (v0 + v1) + (v2 + v3);
            q += (v0*v0 + v1*v1) + (v2*v2 + v3*v3);
        }
    } else {
        #pragma unroll
        for (int nt = 0; nt < 11; nt++) {
            int fb = 176 + 8*nt + 2*tg;
            if (fb < FF) {
                float v0 = acc[nt][0] + bias0;
                float v2 = acc[nt][2] + bias1;
                s += v0 + v2; q += v0*v0 + v2*v2;
            }
            if (fb + 1 < FF) {
                float v1 = acc[nt][1] + bias0;
                float v3 = acc[nt][3] + bias1;
                s += v1 + v3; q += v1*v1 + v3*v3;
            }
        }
    }
    #pragma unroll
    for (int o = 16; o > 0; o >>= 1) {
        s += __shfl_xor_sync(0xffffffffu, s, o);
        q += __shfl_xor_sync(0xffffffffu, q, o);
    }
    CPWAITALL();                       // lnwb landed (own copies); visibility via syncthreads below
    if (lane == 0) { red[warp] = s; red[24 + warp] = q; }
    __syncthreads();
    if (tid < 32) {
        s = (tid < 24) ? red[tid] : 0.f;
        q = (tid < 24) ? red[24 + tid] : 0.f;
        #pragma unroll
        for (int o = 16; o > 0; o >>= 1) {
            s += __shfl_xor_sync(0xffffffffu, s, o);
            q += __shfl_xor_sync(0xffffffffu, q, o);
        }
        if (tid == 0) {
            const float invN = 1.0f / (float)NLN;
            float mu  = s * invN;
            float var = q * invN - mu * mu;
            red[48] = mu;
            red[49] = rsqrtf(var + 1e-5f);
        }
    }
    __syncthreads();
    float mu = red[48], rs = red[49];

    // ---- normalize + store (ln params from smem) ----
    const uint32_t* lnwb = (const uint32_t*)(sm + SLNWB);
    float* po = out + (size_t)bt * NLN;
    int r0 = (16*mg + g) * FF;
    int r1 = r0 + 8 * FF;
    if (ng < 2) {
        #pragma unroll
        for (int nt = 0; nt < 11; nt++) {
            int fb = 88*ng + 8*nt + 2*tg;
            int o0 = r0 + fb, o1 = r1 + fb;
            uint32_t w00 = lnwb[o0],     w01 = lnwb[o0 + 1];
            uint32_t w10 = lnwb[o1],     w11 = lnwb[o1 + 1];
            po[o0]     = (acc[nt][0] + bias0 - mu) * rs * bf16lo(w00) + bf16hi(w00);
            po[o0 + 1] = (acc[nt][1] + bias0 - mu) * rs * bf16lo(w01) + bf16hi(w01);
            po[o1]     = (acc[nt][2] + bias1 - mu) * rs * bf16lo(w10) + bf16hi(w10);
            po[o1 + 1] = (acc[nt][3] + bias1 - mu) * rs * bf16lo(w11) + bf16hi(w11);
        }
    } else {
        #pragma unroll
        for (int nt = 0; nt < 11; nt++) {
            int fb = 176 + 8*nt + 2*tg;
            if (fb < FF) {
                int o0 = r0 + fb, o1 = r1 + fb;
                uint32_t w00 = lnwb[o0], w10 = lnwb[o1];
                po[o0] = (acc[nt][0] + bias0 - mu) * rs * bf16lo(w00) + bf16hi(w00);
                po[o1] = (acc[nt][2] + bias1 - mu) * rs * bf16lo(w10) + bf16hi(w10);
            }
            if (fb + 1 < FF) {
                int o0 = r0 + fb + 1, o1 = r1 + fb + 1;
                uint32_t w01 = lnwb[o0], w11 = lnwb[o1];
                po[o0] = (acc[nt][1] + bias0 - mu) * rs * bf16lo(w01) + bf16hi(w01);
                po[o1] = (acc[nt][3] + bias1 - mu) * rs * bf16lo(w11) + bf16hi(w11);
            }
        }
    }
}

// ---------------- launch ----------------
extern "C" void kernel_launch(void* const* d_in, const int* in_sizes, int n_in,
                              void* d_out, int out_size) {
    const float* x    = (const float*)d_in[0];
    const float* expo = (const float*)d_in[1];
    const float* ipd  = (const float*)d_in[2];
    const float* cw   = (const float*)d_in[3];
    const float* cb   = (const float*)d_in[4];
    const float* lw   = (const float*)d_in[5];
    const float* lb   = (const float*)d_in[6];
    float* out = (float*)d_out;

    wsplit_kernel<<<1, 256>>>(cw);
    lnpack_kernel<<<(NLN + 511) / 512, 512>>>(lw, lb, expo, ipd);
    stats_kernel<<<dim3(BB, FF), 256>>>(x);
    feat_kernel<<<BB * TT, 512>>>(x);

    cudaFuncSetAttribute(conv_ln_kernel,
                         cudaFuncAttributeMaxDynamicSharedMemorySize, SM_TOTAL);
    conv_ln_kernel<<<BB * TT, NTH, SM_TOTAL>>>(cb, out);
}

// round 14
// speedup vs baseline: 1.7737x; 1.0104x over previous
#include <cuda_runtime.h>
#include <cuda_bf16.h>
#include <math.h>
#include <stdint.h>

#define BB 4
#define TT 512
#define FF 257
#define DD 128
#define C2P 20
#define NLN (DD*FF)
#define NTH 768

#define KP   112
#define WSP  120           // A pitch (bf16): 240B rows
#define BSP  264           // B pitch (elements): 528B rows (33x16B)
#define XSP  264           // g_xh/g_xl row pitch (elements)

// smem byte offsets
#define WS_HI 0
#define WS_LO (WS_HI + 128*WSP*2)      // 30720
#define BS_HI (WS_LO + 128*WSP*2)      // 61440
#define BS_LO (BS_HI + KP*BSP*2)       // 120576
#define SLNWB BS_HI                    // lnwb reuses B region after mainloop
#define SRED  (BS_HI + NLN*4)          // 193024
#define SM_TOTAL (SRED + 224)

#define LDSM4(r0,r1,r2,r3,addr) \
  asm volatile("ldmatrix.sync.aligned.m8n8.x4.shared.b16 {%0,%1,%2,%3}, [%4];" \
    : "=r"(r0),"=r"(r1),"=r"(r2),"=r"(r3) : "r"(addr))
#define LDSM4T(r0,r1,r2,r3,addr) \
  asm volatile("ldmatrix.sync.aligned.m8n8.x4.trans.shared.b16 {%0,%1,%2,%3}, [%4];" \
    : "=r"(r0),"=r"(r1),"=r"(r2),"=r"(r3) : "r"(addr))
#define LDSM2T(r0,r1,addr) \
  asm volatile("ldmatrix.sync.aligned.m8n8.x2.trans.shared.b16 {%0,%1}, [%2];" \
    : "=r"(r0),"=r"(r1) : "r"(addr))
#define MMABF16(c,a,b0,b1) \
  asm volatile("mma.sync.aligned.m16n8k16.row.col.f32.bf16.bf16.f32 " \
    "{%0,%1,%2,%3}, {%4,%5,%6,%7}, {%8,%9}, {%0,%1,%2,%3};" \
    : "+f"((c)[0]),"+f"((c)[1]),"+f"((c)[2]),"+f"((c)[3]) \
    : "r"((a)[0]),"r"((a)[1]),"r"((a)[2]),"r"((a)[3]),"r"(b0),"r"(b1))

#define CP16(d,s)    asm volatile("cp.async.cg.shared.global [%0], [%1], 16;" :: "r"(d), "l"(s) : "memory")
#define CP16Z(d,s,z) asm volatile("cp.async.cg.shared.global [%0], [%1], 16, %2;" :: "r"(d), "l"(s), "r"(z) : "memory")
#define CPCOMMIT()   asm volatile("cp.async.commit_group;" ::: "memory")
#define CPWAITALL()  asm volatile("cp.async.wait_group 0;" ::: "memory")

__device__ __forceinline__ uint32_t smem_u32(const void* p) {
    uint32_t a;
    asm("{ .reg .u64 t; cvta.to.shared.u64 t, %1; cvt.u32.u64 %0, t; }" : "=r"(a) : "l"(p));
    return a;
}
__device__ __forceinline__ float bf16lo(uint32_t u) {
    return __bfloat162float(__ushort_as_bfloat16((unsigned short)(u & 0xffffu)));
}
__device__ __forceinline__ float bf16hi(uint32_t u) {
    return __bfloat162float(__ushort_as_bfloat16((unsigned short)(u >> 16)));
}

// ---------------- device scratch ----------------
__device__ float g_mean[BB*FF*8];
__device__ float g_inv[BB*FF];
__device__ float g_s1[FF];
__device__ float g_s2[FF];
__device__ __align__(16) __nv_bfloat16 g_wa_hi[128*WSP];
__device__ __align__(16) __nv_bfloat16 g_wa_lo[128*WSP];
__device__ __align__(16) uint32_t g_lnwb[NLN];
__device__ __align__(16) __nv_bfloat16 g_xh[(size_t)BB*TT*C2P*XSP];
__device__ __align__(16) __nv_bfloat16 g_xl[(size_t)BB*TT*C2P*XSP];

// ---------------- K0a: weight split ----------------
__global__ void wsplit_kernel(const float* __restrict__ conv_w) {
    for (int i = threadIdx.x; i < 128*WSP; i += blockDim.x) {
        int d = i / WSP, j = i - d*WSP;
        float v = (j < 100) ? conv_w[d*100 + j] : 0.f;
        __nv_bfloat16 h = __float2bfloat16(v);
        __nv_bfloat16 l = __float2bfloat16(v - __bfloat162float(h));
        g_wa_hi[i] = h;
        g_wa_lo[i] = l;
    }
}

// ---------------- K0b: ln param pack + sigmoids ----------------
__global__ void lnpack_kernel(const float* __restrict__ lw,
                              const float* __restrict__ lb,
                              const float* __restrict__ expo,
                              const float* __restrict__ ipd) {
    int i = blockIdx.x * blockDim.x + threadIdx.x;
    if (i < NLN) {
        unsigned short w = __bfloat16_as_ushort(__float2bfloat16(lw[i]));
        unsigned short b = __bfloat16_as_ushort(__float2bfloat16(lb[i]));
        g_lnwb[i] = (uint32_t)w | ((uint32_t)b << 16);
    }
    if (i < FF) {
        g_s1[i] = 1.0f / (1.0f + expf(-expo[i]));
        g_s2[i] = 1.0f / (1.0f + expf(-ipd[i]));
    }
}

// ---------------- K1: time stats ----------------
__global__ void stats_kernel(const float* __restrict__ x) {
    int b = blockIdx.x;
    int f = blockIdx.y;
    int tid = threadIdx.x;
    int ch = tid & 7;
    int tl = tid >> 3;

    float s = 0.f, q = 0.f;
    const float* px = x + ((size_t)b * TT * FF + f) * 8 + ch;
    #pragma unroll 4
    for (int t = tl; t < TT; t += 32) {
        float v = px[(size_t)t * FF * 8];
        s += v; q += v * v;
    }
    s += __shfl_xor_sync(0xffffffffu, s, 8);
    q += __shfl_xor_sync(0xffffffffu, q, 8);
    s += __shfl_xor_sync(0xffffffffu, s, 16);
    q += __shfl_xor_sync(0xffffffffu, q, 16);

    __shared__ float sb[8][8], qb[8][8];
    int warp = tid >> 5, lane = tid & 31;
    if (lane < 8) { sb[warp][lane] = s; qb[warp][lane] = q; }
    __syncthreads();

    if (tid == 0) {
        const float invT = 1.0f / (float)TT;
        float ssum[8], qsum[8];
        #pragma unroll
        for (int c = 0; c < 8; c++) {
            float a = 0.f, bq = 0.f;
            #pragma unroll
            for (int w = 0; w < 8; w++) { a += sb[w][c]; bq += qb[w][c]; }
            ssum[c] = a * invT; qsum[c] = bq * invT;
        }
        float tot = 0.f;
        #pragma unroll
        for (int m = 0; m < 4; m++) {
            float mr = ssum[m], mi = ssum[m + 4];
            tot += qsum[m] + qsum[m + 4] - mr * mr - mi * mi;
        }
        #pragma unroll
        for (int j = 0; j < 8; j++) g_mean[(b * FF + f) * 8 + j] = ssum[j];
        g_inv[b * FF + f] = rsqrtf(fmaxf(tot, 1e-10f));
    }
}

// ---------------- K2: SCM pair features -> bf16 hi/lo ----------------
__global__ void feat_kernel(const float* __restrict__ x) {
    int bt = blockIdx.x;
    int b  = bt / TT;
    int tid = threadIdx.x;
    int fi = tid & 255, half = tid >> 8;

    const int ia[10] = {0,0,0,0,1,1,1,2,2,3};
    const int ja[10] = {0,1,2,3,1,2,3,2,3,3};

    for (int f = fi; f < FF; f += 256) {
        const float* px = x + ((size_t)bt * FF + f) * 8;
        const float* mn = g_mean + (b * FF + f) * 8;
        float inv = g_inv[b * FF + f];

        float vr[4], vi[4];
        #pragma unroll
        for (int m = 0; m < 4; m++) {
            vr[m] = (px[m]     - mn[m])     * inv;
            vi[m] = (px[m + 4] - mn[m + 4]) * inv;
        }
        float s1m = 1.0f - g_s1[f];      // mag = a^(1-s1)
        float s2 = g_s2[f];

        size_t rowbase = (size_t)bt * C2P * XSP + f;
        #pragma unroll
        for (int pp = 0; pp < 5; pp++) {
            int p = 5 * half + pp;
            float re = vr[ia[p]] * vr[ja[p]] + vi[ia[p]] * vi[ja[p]];
            float im = vi[ia[p]] * vr[ja[p]] - vr[ia[p]] * vi[ja[p]];
            float a2 = re * re + im * im;
            float mag = (a2 > 0.f) ? exp2f(s1m * 0.5f * log2f(a2)) : 0.f;
            float ang  = atan2f(im, re) * s2;
            float sn, cs;
            sincosf(ang, &sn, &cs);
            float v0 = mag * cs, v1 = mag * sn;
            __nv_bfloat16 h0 = __float2bfloat16(v0);
            __nv_bfloat16 h1 = __float2bfloat16(v1);
            size_t r0 = rowbase + (size_t)(2 * p) * XSP;
            size_t r1 = r0 + XSP;
            g_xh[r0] = h0;
            g_xl[r0] = __float2bfloat16(v0 - __bfloat162float(h0));
            g_xh[r1] = h1;
            g_xl[r1] = __float2bfloat16(v1 - __bfloat162float(h1));
        }
    }
}

// ---------------- K3: HMMA bf16-split conv + LayerNorm ----------------
extern __shared__ char sm[];

__global__ void __launch_bounds__(NTH, 1)
conv_ln_kernel(const float* __restrict__ conv_b,
               float* __restrict__ out) {
    int bt = blockIdx.x;
    int b  = bt / TT;
    int t  = bt % TT;
    int tid = threadIdx.x;
    int warp = tid >> 5, lane = tid & 31;
    int g = lane >> 2, tg = lane & 3;
    int mg = warp & 7;          // d rows [16mg, 16mg+16)
    int ng = warp >> 3;         // f cols [88ng, 88ng+88)

    uint32_t sb = smem_u32(sm);

    // ---- stage A via cp.async ----
    for (int i = tid * 16; i < 128*WSP*2; i += NTH * 16) {
        CP16(sb + WS_HI + i, (const char*)g_wa_hi + i);
        CP16(sb + WS_LO + i, (const char*)g_wa_lo + i);
    }

    // ---- stage B rows via cp.async (zero-fill invalid rows) ----
    for (int j = warp; j < KP; j += 24) {
        int c = j / 5, k = j - c * 5;
        int tt = t + k - 2;
        bool jv = (j < 100) && (tt >= 0) && (tt < TT);
        size_t ro = jv ? ((size_t)((b*TT + tt)*C2P + c) * XSP) * 2 : 0;
        const char* sh = (const char*)g_xh + ro;
        const char* sl = (const char*)g_xl + ro;
        uint32_t dh = sb + BS_HI + j * (BSP*2);
        uint32_t dl = sb + BS_LO + j * (BSP*2);
        int sz = jv ? 16 : 0;
        for (int ch = lane * 16; ch < BSP*2; ch += 32 * 16) {
            CP16Z(dh + ch, sh + ch, sz);
            CP16Z(dl + ch, sl + ch, sz);
        }
    }
    CPCOMMIT();
    CPWAITALL();
    __syncthreads();

    // ---- mainloop ----
    float acc[11][4];
    #pragma unroll
    for (int nt = 0; nt < 11; nt++)
        #pragma unroll
        for (int ci = 0; ci < 4; ci++) acc[nt][ci] = 0.f;

    int aRow = (lane & 7) + 8 * ((lane >> 3) & 1);
    int aK   = (lane >> 4) * 8;
    uint32_t aoff = sb + WS_HI + (uint32_t)(((16*mg + aRow) * WSP + aK) * 2);
    // x4-trans B addressing: lanes 0-7: k0-7 tile0; 8-15: k8-15 tile0;
    //                        16-23: k0-7 tile1; 24-31: k8-15 tile1
    int kRow = (lane & 7) + 8 * ((lane >> 3) & 1);
    uint32_t boff4 = sb + BS_HI
                   + (uint32_t)((kRow * BSP + 88*ng) * 2)
                   + (uint32_t)((lane >> 4) * 16);
    // x2 tail addressing (lanes 0-15 meaningful)
    uint32_t boff2 = sb + BS_HI + (uint32_t)((kRow * BSP + 88*ng + 80) * 2);

    for (int kt = 0; kt < 7; kt++) {
        uint32_t ah[4], al[4];
        uint32_t a = aoff + kt * 32;
        LDSM4(ah[0], ah[1], ah[2], ah[3], a);
        LDSM4(al[0], al[1], al[2], al[3], a + (WS_LO - WS_HI));
        uint32_t krowoff = kt * (16*BSP*2);
        #pragma unroll
        for (int np = 0; np < 5; np++) {
            uint32_t badr = boff4 + krowoff + np * 32;
            uint32_t bh[4], bl[4];
            LDSM4T(bh[0], bh[1], bh[2], bh[3], badr);
            LDSM4T(bl[0], bl[1], bl[2], bl[3], badr + (BS_LO - BS_HI));
            int nt = 2 * np;
            MMABF16(acc[nt],     ah, bh[0], bh[1]);
            MMABF16(acc[nt + 1], ah, bh[2], bh[3]);
            MMABF16(acc[nt],     ah, bl[0], bl[1]);
            MMABF16(acc[nt + 1], ah, bl[2], bl[3]);
            MMABF16(acc[nt],     al, bh[0], bh[1]);
            MMABF16(acc[nt + 1], al, bh[2], bh[3]);
        }
        {   // tail n-tile 10
            uint32_t badr = boff2 + krowoff;
            uint32_t bh0, bh1, bl0, bl1;
            LDSM2T(bh0, bh1, badr);
            LDSM2T(bl0, bl1, badr + (BS_LO - BS_HI));
            MMABF16(acc[10], ah, bh0, bh1);
            MMABF16(acc[10], ah, bl0, bl1);
            MMABF16(acc[10], al, bh0, bh1);
        }
    }
    __syncthreads();   // B region dead

    // ---- lnwb copy via cp.async (hides behind stats reduction) ----
    for (int i = tid * 16; i < NLN * 4; i += NTH * 16)
        CP16(sb + SLNWB + i, (const char*)g_lnwb + i);
    CPCOMMIT();

    // ---- bias ----
    float bias0 = conv_b[16*mg + g];
    float bias1 = conv_b[16*mg + 8 + g];

    // ---- LN stats from registers ----
    float* red = (float*)(sm + SRED);
    float s = 0.f, q = 0.f;
    if (ng < 2) {
        #pragma unroll
        for (int nt = 0; nt < 11; nt++) {
            float v0 = acc[nt][0] + bias0;
            float v1 = acc[nt][1] + bias0;
            float v2 = acc[nt][2] + bias1;
            float v3 = acc[nt][3] + bias1;
            s += (v0 + v1) + (v2 + v3);
            q += (v0*v0 + v1*v1) + (v2*v2 + v3*v3);
        }
    } else {
        #pragma unroll
        for (int nt = 0; nt < 11; nt++) {
            int fb = 176 + 8*nt + 2*tg;
            if (fb < FF) {
                float v0 = acc[nt][0] + bias0;
                float v2 = acc[nt][2] + bias1;
                s += v0 + v2; q += v0*v0 + v2*v2;
            }
            if (fb + 1 < FF) {
                float v1 = acc[nt][1] + bias0;
                float v3 = acc[nt][3] + bias1;
                s += v1 + v3; q += v1*v1 + v3*v3;
            }
        }
    }
    #pragma unroll
    for (int o = 16; o > 0; o >>= 1) {
        s += __shfl_xor_sync(0xffffffffu, s, o);
        q += __shfl_xor_sync(0xffffffffu, q, o);
    }
    CPWAITALL();
    if (lane == 0) { red[warp] = s; red[24 + warp] = q; }
    __syncthreads();
    if (tid < 32) {
        s = (tid < 24) ? red[tid] : 0.f;
        q = (tid < 24) ? red[24 + tid] : 0.f;
        #pragma unroll
        for (int o = 16; o > 0; o >>= 1) {
            s += __shfl_xor_sync(0xffffffffu, s, o);
            q += __shfl_xor_sync(0xffffffffu, q, o);
        }
        if (tid == 0) {
            const float invN = 1.0f / (float)NLN;
            float mu  = s * invN;
            float var = q * invN - mu * mu;
            red[48] = mu;
            red[49] = rsqrtf(var + 1e-5f);
        }
    }
    __syncthreads();
    float mu = red[48], rs = red[49];

    // ---- normalize + store ----
    const uint32_t* lnwb = (const uint32_t*)(sm + SLNWB);
    float* po = out + (size_t)bt * NLN;
    int r0 = (16*mg + g) * FF;
    int r1 = r0 + 8 * FF;
    if (ng < 2) {
        #pragma unroll
        for (int nt = 0; nt < 11; nt++) {
            int fb = 88*ng + 8*nt + 2*tg;
            int o0 = r0 + fb, o1 = r1 + fb;
            uint32_t w00 = lnwb[o0],     w01 = lnwb[o0 + 1];
            uint32_t w10 = lnwb[o1],     w11 = lnwb[o1 + 1];
            po[o0]     = (acc[nt][0] + bias0 - mu) * rs * bf16lo(w00) + bf16hi(w00);
            po[o0 + 1] = (acc[nt][1] + bias0 - mu) * rs * bf16lo(w01) + bf16hi(w01);
            po[o1]     = (acc[nt][2] + bias1 - mu) * rs * bf16lo(w10) + bf16hi(w10);
            po[o1 + 1] = (acc[nt][3] + bias1 - mu) * rs * bf16lo(w11) + bf16hi(w11);
        }
    } else {
        #pragma unroll
        for (int nt = 0; nt < 11; nt++) {
            int fb = 176 + 8*nt + 2*tg;
            if (fb < FF) {
                int o0 = r0 + fb, o1 = r1 + fb;
                uint32_t w00 = lnwb[o0], w10 = lnwb[o1];
                po[o0] = (acc[nt][0] + bias0 - mu) * rs * bf16lo(w00) + bf16hi(w00);
                po[o1] = (acc[nt][2] + bias1 - mu) * rs * bf16lo(w10) + bf16hi(w10);
            }
            if (fb + 1 < FF) {
                int o0 = r0 + fb + 1, o1 = r1 + fb + 1;
                uint32_t w01 = lnwb[o0], w11 = lnwb[o1];
                po[o0] = (acc[nt][1] + bias0 - mu) * rs * bf16lo(w01) + bf16hi(w01);
                po[o1] = (acc[nt][3] + bias1 - mu) * rs * bf16lo(w11) + bf16hi(w11);
            }
        }
    }
}

// ---------------- launch ----------------
extern "C" void kernel_launch(void* const* d_in, const int* in_sizes, int n_in,
                              void* d_out, int out_size) {
    const float* x    = (const float*)d_in[0];
    const float* expo = (const float*)d_in[1];
    const float* ipd  = (const float*)d_in[2];
    const float* cw   = (const float*)d_in[3];
    const float* cb   = (const float*)d_in[4];
    const float* lw   = (const float*)d_in[5];
    const float* lb   = (const float*)d_in[6];
    float* out = (float*)d_out;

    wsplit_kernel<<<1, 256>>>(cw);
    lnpack_kernel<<<(NLN + 511) / 512, 512>>>(lw, lb, expo, ipd);
    stats_kernel<<<dim3(BB, FF), 256>>>(x);
    feat_kernel<<<BB * TT, 512>>>(x);

    cudaFuncSetAttribute(conv_ln_kernel,
                         cudaFuncAttributeMaxDynamicSharedMemorySize, SM_TOTAL);
    conv_ln_kernel<<<BB * TT, NTH, SM_TOTAL>>>(cb, out);
}

// round 15
// speedup vs baseline: 1.9064x; 1.0748x over previous
#include <cuda_runtime.h>
#include <cuda_bf16.h>
#include <math.h>
#include <stdint.h>

#define BB 4
#define TT 512
#define FF 257
#define DD 128
#define C2P 20
#define NLN (DD*FF)
#define NTH 384

#define KP   112
#define WSP  120           // A pitch (bf16): 240B rows
#define BSP  264           // B pitch (elements): 528B rows (33x16B)
#define XSP  264           // g_xh/g_xl row pitch (elements)

// smem byte offsets
#define WS_HI 0
#define WS_LO (WS_HI + 128*WSP*2)      // 30720
#define BS_HI (WS_LO + 128*WSP*2)      // 61440
#define BS_LO (BS_HI + KP*BSP*2)       // 120576
#define SLNWB BS_HI                    // lnwb reuses B region after mainloop
#define SRED  (BS_HI + NLN*4)          // 193024
#define SM_TOTAL (SRED + 224)

#define LDSM4(r0,r1,r2,r3,addr) \
  asm volatile("ldmatrix.sync.aligned.m8n8.x4.shared.b16 {%0,%1,%2,%3}, [%4];" \
    : "=r"(r0),"=r"(r1),"=r"(r2),"=r"(r3) : "r"(addr))
#define LDSM4T(r0,r1,r2,r3,addr) \
  asm volatile("ldmatrix.sync.aligned.m8n8.x4.trans.shared.b16 {%0,%1,%2,%3}, [%4];" \
    : "=r"(r0),"=r"(r1),"=r"(r2),"=r"(r3) : "r"(addr))
#define LDSM2T(r0,r1,addr) \
  asm volatile("ldmatrix.sync.aligned.m8n8.x2.trans.shared.b16 {%0,%1}, [%2];" \
    : "=r"(r0),"=r"(r1) : "r"(addr))
#define MMABF16(c,a,b0,b1) \
  asm volatile("mma.sync.aligned.m16n8k16.row.col.f32.bf16.bf16.f32 " \
    "{%0,%1,%2,%3}, {%4,%5,%6,%7}, {%8,%9}, {%0,%1,%2,%3};" \
    : "+f"((c)[0]),"+f"((c)[1]),"+f"((c)[2]),"+f"((c)[3]) \
    : "r"((a)[0]),"r"((a)[1]),"r"((a)[2]),"r"((a)[3]),"r"(b0),"r"(b1))

#define CP16(d,s)    asm volatile("cp.async.cg.shared.global [%0], [%1], 16;" :: "r"(d), "l"(s) : "memory")
#define CP16Z(d,s,z) asm volatile("cp.async.cg.shared.global [%0], [%1], 16, %2;" :: "r"(d), "l"(s), "r"(z) : "memory")
#define CPCOMMIT()   asm volatile("cp.async.commit_group;" ::: "memory")
#define CPWAITALL()  asm volatile("cp.async.wait_group 0;" ::: "memory")

__device__ __forceinline__ uint32_t smem_u32(const void* p) {
    uint32_t a;
    asm("{ .reg .u64 t; cvta.to.shared.u64 t, %1; cvt.u32.u64 %0, t; }" : "=r"(a) : "l"(p));
    return a;
}
__device__ __forceinline__ float bf16lo(uint32_t u) {
    return __bfloat162float(__ushort_as_bfloat16((unsigned short)(u & 0xffffu)));
}
__device__ __forceinline__ float bf16hi(uint32_t u) {
    return __bfloat162float(__ushort_as_bfloat16((unsigned short)(u >> 16)));
}

// ---------------- device scratch ----------------
__device__ float g_mean[BB*FF*8];
__device__ float g_inv[BB*FF];
__device__ float g_s1[FF];
__device__ float g_s2[FF];
__device__ __align__(16) __nv_bfloat16 g_wa_hi[128*WSP];
__device__ __align__(16) __nv_bfloat16 g_wa_lo[128*WSP];
__device__ __align__(16) uint32_t g_lnwb[NLN];
__device__ __align__(16) __nv_bfloat16 g_xh[(size_t)BB*TT*C2P*XSP];
__device__ __align__(16) __nv_bfloat16 g_xl[(size_t)BB*TT*C2P*XSP];

// ---------------- K0a: weight split ----------------
__global__ void wsplit_kernel(const float* __restrict__ conv_w) {
    for (int i = threadIdx.x; i < 128*WSP; i += blockDim.x) {
        int d = i / WSP, j = i - d*WSP;
        float v = (j < 100) ? conv_w[d*100 + j] : 0.f;
        __nv_bfloat16 h = __float2bfloat16(v);
        __nv_bfloat16 l = __float2bfloat16(v - __bfloat162float(h));
        g_wa_hi[i] = h;
        g_wa_lo[i] = l;
    }
}

// ---------------- K0b: ln param pack + sigmoids ----------------
__global__ void lnpack_kernel(const float* __restrict__ lw,
                              const float* __restrict__ lb,
                              const float* __restrict__ expo,
                              const float* __restrict__ ipd) {
    int i = blockIdx.x * blockDim.x + threadIdx.x;
    if (i < NLN) {
        unsigned short w = __bfloat16_as_ushort(__float2bfloat16(lw[i]));
        unsigned short b = __bfloat16_as_ushort(__float2bfloat16(lb[i]));
        g_lnwb[i] = (uint32_t)w | ((uint32_t)b << 16);
    }
    if (i < FF) {
        g_s1[i] = 1.0f / (1.0f + expf(-expo[i]));
        g_s2[i] = 1.0f / (1.0f + expf(-ipd[i]));
    }
}

// ---------------- K1: time stats ----------------
__global__ void stats_kernel(const float* __restrict__ x) {
    int b = blockIdx.x;
    int f = blockIdx.y;
    int tid = threadIdx.x;
    int ch = tid & 7;
    int tl = tid >> 3;

    float s = 0.f, q = 0.f;
    const float* px = x + ((size_t)b * TT * FF + f) * 8 + ch;
    #pragma unroll 4
    for (int t = tl; t < TT; t += 32) {
        float v = px[(size_t)t * FF * 8];
        s += v; q += v * v;
    }
    s += __shfl_xor_sync(0xffffffffu, s, 8);
    q += __shfl_xor_sync(0xffffffffu, q, 8);
    s += __shfl_xor_sync(0xffffffffu, s, 16);
    q += __shfl_xor_sync(0xffffffffu, q, 16);

    __shared__ float sb[8][8], qb[8][8];
    int warp = tid >> 5, lane = tid & 31;
    if (lane < 8) { sb[warp][lane] = s; qb[warp][lane] = q; }
    __syncthreads();

    if (tid == 0) {
        const float invT = 1.0f / (float)TT;
        float ssum[8], qsum[8];
        #pragma unroll
        for (int c = 0; c < 8; c++) {
            float a = 0.f, bq = 0.f;
            #pragma unroll
            for (int w = 0; w < 8; w++) { a += sb[w][c]; bq += qb[w][c]; }
            ssum[c] = a * invT; qsum[c] = bq * invT;
        }
        float tot = 0.f;
        #pragma unroll
        for (int m = 0; m < 4; m++) {
            float mr = ssum[m], mi = ssum[m + 4];
            tot += qsum[m] + qsum[m + 4] - mr * mr - mi * mi;
        }
        #pragma unroll
        for (int j = 0; j < 8; j++) g_mean[(b * FF + f) * 8 + j] = ssum[j];
        g_inv[b * FF + f] = rsqrtf(fmaxf(tot, 1e-10f));
    }
}

// ---------------- K2: SCM pair features -> bf16 hi/lo ----------------
__global__ void feat_kernel(const float* __restrict__ x) {
    int bt = blockIdx.x;
    int b  = bt / TT;
    int tid = threadIdx.x;
    int fi = tid & 255, half = tid >> 8;

    const int ia[10] = {0,0,0,0,1,1,1,2,2,3};
    const int ja[10] = {0,1,2,3,1,2,3,2,3,3};

    for (int f = fi; f < FF; f += 256) {
        const float* px = x + ((size_t)bt * FF + f) * 8;
        const float* mn = g_mean + (b * FF + f) * 8;
        float inv = g_inv[b * FF + f];

        float vr[4], vi[4];
        #pragma unroll
        for (int m = 0; m < 4; m++) {
            vr[m] = (px[m]     - mn[m])     * inv;
            vi[m] = (px[m + 4] - mn[m + 4]) * inv;
        }
        float s1m = 1.0f - g_s1[f];
        float s2 = g_s2[f];

        size_t rowbase = (size_t)bt * C2P * XSP + f;
        #pragma unroll
        for (int pp = 0; pp < 5; pp++) {
            int p = 5 * half + pp;
            float re = vr[ia[p]] * vr[ja[p]] + vi[ia[p]] * vi[ja[p]];
            float im = vi[ia[p]] * vr[ja[p]] - vr[ia[p]] * vi[ja[p]];
            float a2 = re * re + im * im;
            float mag = (a2 > 0.f) ? exp2f(s1m * 0.5f * log2f(a2)) : 0.f;
            float ang  = atan2f(im, re) * s2;
            float sn, cs;
            sincosf(ang, &sn, &cs);
            float v0 = mag * cs, v1 = mag * sn;
            __nv_bfloat16 h0 = __float2bfloat16(v0);
            __nv_bfloat16 h1 = __float2bfloat16(v1);
            size_t r0 = rowbase + (size_t)(2 * p) * XSP;
            size_t r1 = r0 + XSP;
            g_xh[r0] = h0;
            g_xl[r0] = __float2bfloat16(v0 - __bfloat162float(h0));
            g_xh[r1] = h1;
            g_xl[r1] = __float2bfloat16(v1 - __bfloat162float(h1));
        }
    }
}

// ---------------- K3: HMMA bf16-split conv + LayerNorm ----------------
// 12 warps = 4 m-groups (m32) x 3 n-groups (88 f). B fragments shared
// across 2 m-tiles per warp -> half the B LDSM traffic, 2x MMA ILP per load.
extern __shared__ char sm[];

__global__ void __launch_bounds__(NTH, 1)
conv_ln_kernel(const float* __restrict__ conv_b,
               float* __restrict__ out) {
    int bt = blockIdx.x;
    int b  = bt / TT;
    int t  = bt % TT;
    int tid = threadIdx.x;
    int warp = tid >> 5, lane = tid & 31;
    int g = lane >> 2, tg = lane & 3;
    int mg = warp & 3;          // d rows [32mg, 32mg+32)
    int ng = warp >> 2;         // f cols [88ng, 88ng+88)

    uint32_t sb = smem_u32(sm);

    // ---- stage A via cp.async ----
    for (int i = tid * 16; i < 128*WSP*2; i += NTH * 16) {
        CP16(sb + WS_HI + i, (const char*)g_wa_hi + i);
        CP16(sb + WS_LO + i, (const char*)g_wa_lo + i);
    }

    // ---- stage B rows via cp.async (zero-fill invalid rows) ----
    for (int j = warp; j < KP; j += 12) {
        int c = j / 5, k = j - c * 5;
        int tt = t + k - 2;
        bool jv = (j < 100) && (tt >= 0) && (tt < TT);
        size_t ro = jv ? ((size_t)((b*TT + tt)*C2P + c) * XSP) * 2 : 0;
        const char* sh = (const char*)g_xh + ro;
        const char* sl = (const char*)g_xl + ro;
        uint32_t dh = sb + BS_HI + j * (BSP*2);
        uint32_t dl = sb + BS_LO + j * (BSP*2);
        int sz = jv ? 16 : 0;
        for (int ch = lane * 16; ch < BSP*2; ch += 32 * 16) {
            CP16Z(dh + ch, sh + ch, sz);
            CP16Z(dl + ch, sl + ch, sz);
        }
    }
    CPCOMMIT();
    CPWAITALL();
    __syncthreads();

    // ---- mainloop ----
    float acc[2][11][4];
    #pragma unroll
    for (int mt = 0; mt < 2; mt++)
        #pragma unroll
        for (int nt = 0; nt < 11; nt++)
            #pragma unroll
            for (int ci = 0; ci < 4; ci++) acc[mt][nt][ci] = 0.f;

    int aRow = (lane & 7) + 8 * ((lane >> 3) & 1);
    int aK   = (lane >> 4) * 8;
    uint32_t aoff = sb + WS_HI + (uint32_t)(((32*mg + aRow) * WSP + aK) * 2);
    int kRow = (lane & 7) + 8 * ((lane >> 3) & 1);
    uint32_t boff4 = sb + BS_HI
                   + (uint32_t)((kRow * BSP + 88*ng) * 2)
                   + (uint32_t)((lane >> 4) * 16);
    uint32_t boff2 = sb + BS_HI + (uint32_t)((kRow * BSP + 88*ng + 80) * 2);

    for (int kt = 0; kt < 7; kt++) {
        uint32_t ah[2][4], al[2][4];
        #pragma unroll
        for (int mt = 0; mt < 2; mt++) {
            uint32_t a = aoff + mt * (16*WSP*2) + kt * 32;
            LDSM4(ah[mt][0], ah[mt][1], ah[mt][2], ah[mt][3], a);
            LDSM4(al[mt][0], al[mt][1], al[mt][2], al[mt][3], a + (WS_LO - WS_HI));
        }
        uint32_t krowoff = kt * (16*BSP*2);
        #pragma unroll
        for (int np = 0; np < 5; np++) {
            uint32_t badr = boff4 + krowoff + np * 32;
            uint32_t bh[4], bl[4];
            LDSM4T(bh[0], bh[1], bh[2], bh[3], badr);
            LDSM4T(bl[0], bl[1], bl[2], bl[3], badr + (BS_LO - BS_HI));
            int nt = 2 * np;
            #pragma unroll
            for (int mt = 0; mt < 2; mt++) {
                MMABF16(acc[mt][nt],     ah[mt], bh[0], bh[1]);
                MMABF16(acc[mt][nt + 1], ah[mt], bh[2], bh[3]);
                MMABF16(acc[mt][nt],     ah[mt], bl[0], bl[1]);
                MMABF16(acc[mt][nt + 1], ah[mt], bl[2], bl[3]);
                MMABF16(acc[mt][nt],     al[mt], bh[0], bh[1]);
                MMABF16(acc[mt][nt + 1], al[mt], bh[2], bh[3]);
            }
        }
        {   // tail n-tile 10
            uint32_t badr = boff2 + krowoff;
            uint32_t bh0, bh1, bl0, bl1;
            LDSM2T(bh0, bh1, badr);
            LDSM2T(bl0, bl1, badr + (BS_LO - BS_HI));
            #pragma unroll
            for (int mt = 0; mt < 2; mt++) {
                MMABF16(acc[mt][10], ah[mt], bh0, bh1);
                MMABF16(acc[mt][10], ah[mt], bl0, bl1);
                MMABF16(acc[mt][10], al[mt], bh0, bh1);
            }
        }
    }
    __syncthreads();   // B region dead

    // ---- lnwb copy via cp.async (hides behind stats reduction) ----
    for (int i = tid * 16; i < NLN * 4; i += NTH * 16)
        CP16(sb + SLNWB + i, (const char*)g_lnwb + i);
    CPCOMMIT();

    // ---- bias ----
    float bias[2][2];
    #pragma unroll
    for (int mt = 0; mt < 2; mt++) {
        int r = 32*mg + 16*mt + g;
        bias[mt][0] = conv_b[r];
        bias[mt][1] = conv_b[r + 8];
    }

    // ---- LN stats from registers ----
    float* red = (float*)(sm + SRED);
    float s = 0.f, q = 0.f;
    if (ng < 2) {
        #pragma unroll
        for (int mt = 0; mt < 2; mt++)
            #pragma unroll
            for (int nt = 0; nt < 11; nt++) {
                float v0 = acc[mt][nt][0] + bias[mt][0];
                float v1 = acc[mt][nt][1] + bias[mt][0];
                float v2 = acc[mt][nt][2] + bias[mt][1];
                float v3 = acc[mt][nt][3] + bias[mt][1];
                s += (v0 + v1) + (v2 + v3);
                q += (v0*v0 + v1*v1) + (v2*v2 + v3*v3);
            }
    } else {
        #pragma unroll
        for (int mt = 0; mt < 2; mt++)
            #pragma unroll
            for (int nt = 0; nt < 11; nt++) {
                int fb = 176 + 8*nt + 2*tg;
                if (fb < FF) {
                    float v0 = acc[mt][nt][0] + bias[mt][0];
                    float v2 = acc[mt][nt][2] + bias[mt][1];
                    s += v0 + v2; q += v0*v0 + v2*v2;
                }
                if (fb + 1 < FF) {
                    float v1 = acc[mt][nt][1] + bias[mt][0];
                    float v3 = acc[mt][nt][3] + bias[mt][1];
                    s += v1 + v3; q += v1*v1 + v3*v3;
                }
            }
    }
    #pragma unroll
    for (int o = 16; o > 0; o >>= 1) {
        s += __shfl_xor_sync(0xffffffffu, s, o);
        q += __shfl_xor_sync(0xffffffffu, q, o);
    }
    CPWAITALL();
    if (lane == 0) { red[warp] = s; red[12 + warp] = q; }
    __syncthreads();
    if (tid < 32) {
        s = (tid < 12) ? red[tid] : 0.f;
        q = (tid < 12) ? red[12 + tid] : 0.f;
        #pragma unroll
        for (int o = 8; o > 0; o >>= 1) {
            s += __shfl_xor_sync(0xffffffffu, s, o);
            q += __shfl_xor_sync(0xffffffffu, q, o);
        }
        if (tid == 0) {
            const float invN = 1.0f / (float)NLN;
            float mu  = s * invN;
            float var = q * invN - mu * mu;
            red[24] = mu;
            red[25] = rsqrtf(var + 1e-5f);
        }
    }
    __syncthreads();
    float mu = red[24], rs = red[25];

    // ---- normalize + store ----
    const uint32_t* lnwb = (const uint32_t*)(sm + SLNWB);
    float* po = out + (size_t)bt * NLN;
    #pragma unroll
    for (int mt = 0; mt < 2; mt++) {
        int r0 = (32*mg + 16*mt + g) * FF;
        int r1 = r0 + 8 * FF;
        if (ng < 2) {
            #pragma unroll
            for (int nt = 0; nt < 11; nt++) {
                int fb = 88*ng + 8*nt + 2*tg;
                int o0 = r0 + fb, o1 = r1 + fb;
                uint32_t w00 = lnwb[o0],     w01 = lnwb[o0 + 1];
                uint32_t w10 = lnwb[o1],     w11 = lnwb[o1 + 1];
                po[o0]     = (acc[mt][nt][0] + bias[mt][0] - mu) * rs * bf16lo(w00) + bf16hi(w00);
                po[o0 + 1] = (acc[mt][nt][1] + bias[mt][0] - mu) * rs * bf16lo(w01) + bf16hi(w01);
                po[o1]     = (acc[mt][nt][2] + bias[mt][1] - mu) * rs * bf16lo(w10) + bf16hi(w10);
                po[o1 + 1] = (acc[mt][nt][3] + bias[mt][1] - mu) * rs * bf16lo(w11) + bf16hi(w11);
            }
        } else {
            #pragma unroll
            for (int nt = 0; nt < 11; nt++) {
                int fb = 176 + 8*nt + 2*tg;
                if (fb < FF) {
                    int o0 = r0 + fb, o1 = r1 + fb;
                    uint32_t w00 = lnwb[o0], w10 = lnwb[o1];
                    po[o0] = (acc[mt][nt][0] + bias[mt][0] - mu) * rs * bf16lo(w00) + bf16hi(w00);
                    po[o1] = (acc[mt][nt][2] + bias[mt][1] - mu) * rs * bf16lo(w10) + bf16hi(w10);
                }
                if (fb + 1 < FF) {
                    int o0 = r0 + fb + 1, o1 = r1 + fb + 1;
                    uint32_t w01 = lnwb[o0], w11 = lnwb[o1];
                    po[o0] = (acc[mt][nt][1] + bias[mt][0] - mu) * rs * bf16lo(w01) + bf16hi(w01);
                    po[o1] = (acc[mt][nt][3] + bias[mt][1] - mu) * rs * bf16lo(w11) + bf16hi(w11);
                }
            }
        }
    }
}

// ---------------- launch ----------------
extern "C" void kernel_launch(void* const* d_in, const int* in_sizes, int n_in,
                              void* d_out, int out_size) {
    const float* x    = (const float*)d_in[0];
    const float* expo = (const float*)d_in[1];
    const float* ipd  = (const float*)d_in[2];
    const float* cw   = (const float*)d_in[3];
    const float* cb   = (const float*)d_in[4];
    const float* lw   = (const float*)d_in[5];
    const float* lb   = (const float*)d_in[6];
    float* out = (float*)d_out;

    wsplit_kernel<<<1, 256>>>(cw);
    lnpack_kernel<<<(NLN + 511) / 512, 512>>>(lw, lb, expo, ipd);
    stats_kernel<<<dim3(BB, FF), 256>>>(x);
    feat_kernel<<<BB * TT, 512>>>(x);

    cudaFuncSetAttribute(conv_ln_kernel,
                         cudaFuncAttributeMaxDynamicSharedMemorySize, SM_TOTAL);
    conv_ln_kernel<<<BB * TT, NTH, SM_TOTAL>>>(cb, out);
}

// round 16
// speedup vs baseline: 2.0580x; 1.0795x over previous
#include <cuda_runtime.h>
#include <cuda_bf16.h>
#include <math.h>
#include <stdint.h>

#define BB 4
#define TT 512
#define FF 257
#define DD 128
#define C2P 20
#define NLN (DD*FF)
#define NTH 384

#define KP   112
#define WSP  120           // A pitch (bf16): 240B rows
#define BSP  264           // B pitch (elements): 528B rows (33x16B)
#define XSP  264           // g_xh/g_xl row pitch (elements)

// smem byte offsets
#define WS_HI 0
#define WS_LO (WS_HI + 128*WSP*2)      // 30720
#define BS_HI (WS_LO + 128*WSP*2)      // 61440
#define BS_LO (BS_HI + KP*BSP*2)       // 120576
#define BS_END (BS_LO + KP*BSP*2)      // 179712
#define SRED  BS_END                   // red buffer beyond staging
#define SM_TOTAL (SRED + 224)          // 179936
// y_s (128*257 floats = 131584 B) reuses [0, 131584) after mainloop

#define LDSM4(r0,r1,r2,r3,addr) \
  asm volatile("ldmatrix.sync.aligned.m8n8.x4.shared.b16 {%0,%1,%2,%3}, [%4];" \
    : "=r"(r0),"=r"(r1),"=r"(r2),"=r"(r3) : "r"(addr))
#define LDSM4T(r0,r1,r2,r3,addr) \
  asm volatile("ldmatrix.sync.aligned.m8n8.x4.trans.shared.b16 {%0,%1,%2,%3}, [%4];" \
    : "=r"(r0),"=r"(r1),"=r"(r2),"=r"(r3) : "r"(addr))
#define LDSM2T(r0,r1,addr) \
  asm volatile("ldmatrix.sync.aligned.m8n8.x2.trans.shared.b16 {%0,%1}, [%2];" \
    : "=r"(r0),"=r"(r1) : "r"(addr))
#define MMABF16(c,a,b0,b1) \
  asm volatile("mma.sync.aligned.m16n8k16.row.col.f32.bf16.bf16.f32 " \
    "{%0,%1,%2,%3}, {%4,%5,%6,%7}, {%8,%9}, {%0,%1,%2,%3};" \
    : "+f"((c)[0]),"+f"((c)[1]),"+f"((c)[2]),"+f"((c)[3]) \
    : "r"((a)[0]),"r"((a)[1]),"r"((a)[2]),"r"((a)[3]),"r"(b0),"r"(b1))

#define CP16(d,s)    asm volatile("cp.async.cg.shared.global [%0], [%1], 16;" :: "r"(d), "l"(s) : "memory")
#define CP16Z(d,s,z) asm volatile("cp.async.cg.shared.global [%0], [%1], 16, %2;" :: "r"(d), "l"(s), "r"(z) : "memory")
#define CPCOMMIT()   asm volatile("cp.async.commit_group;" ::: "memory")
#define CPWAITALL()  asm volatile("cp.async.wait_group 0;" ::: "memory")

__device__ __forceinline__ uint32_t smem_u32(const void* p) {
    uint32_t a;
    asm("{ .reg .u64 t; cvta.to.shared.u64 t, %1; cvt.u32.u64 %0, t; }" : "=r"(a) : "l"(p));
    return a;
}
__device__ __forceinline__ float bf16lo(uint32_t u) {
    return __bfloat162float(__ushort_as_bfloat16((unsigned short)(u & 0xffffu)));
}
__device__ __forceinline__ float bf16hi(uint32_t u) {
    return __bfloat162float(__ushort_as_bfloat16((unsigned short)(u >> 16)));
}

// ---------------- device scratch ----------------
__device__ float g_mean[BB*FF*8];
__device__ float g_inv[BB*FF];
__device__ float g_s1[FF];
__device__ float g_s2[FF];
__device__ __align__(16) __nv_bfloat16 g_wa_hi[128*WSP];
__device__ __align__(16) __nv_bfloat16 g_wa_lo[128*WSP];
__device__ __align__(16) uint32_t g_lnwb[NLN];
__device__ __align__(16) __nv_bfloat16 g_xh[(size_t)BB*TT*C2P*XSP];
__device__ __align__(16) __nv_bfloat16 g_xl[(size_t)BB*TT*C2P*XSP];

// ---------------- K0a: weight split ----------------
__global__ void wsplit_kernel(const float* __restrict__ conv_w) {
    for (int i = threadIdx.x; i < 128*WSP; i += blockDim.x) {
        int d = i / WSP, j = i - d*WSP;
        float v = (j < 100) ? conv_w[d*100 + j] : 0.f;
        __nv_bfloat16 h = __float2bfloat16(v);
        __nv_bfloat16 l = __float2bfloat16(v - __bfloat162float(h));
        g_wa_hi[i] = h;
        g_wa_lo[i] = l;
    }
}

// ---------------- K0b: ln param pack + sigmoids ----------------
__global__ void lnpack_kernel(const float* __restrict__ lw,
                              const float* __restrict__ lb,
                              const float* __restrict__ expo,
                              const float* __restrict__ ipd) {
    int i = blockIdx.x * blockDim.x + threadIdx.x;
    if (i < NLN) {
        unsigned short w = __bfloat16_as_ushort(__float2bfloat16(lw[i]));
        unsigned short b = __bfloat16_as_ushort(__float2bfloat16(lb[i]));
        g_lnwb[i] = (uint32_t)w | ((uint32_t)b << 16);
    }
    if (i < FF) {
        g_s1[i] = 1.0f / (1.0f + expf(-expo[i]));
        g_s2[i] = 1.0f / (1.0f + expf(-ipd[i]));
    }
}

// ---------------- K1: time stats ----------------
__global__ void stats_kernel(const float* __restrict__ x) {
    int b = blockIdx.x;
    int f = blockIdx.y;
    int tid = threadIdx.x;
    int ch = tid & 7;
    int tl = tid >> 3;

    float s = 0.f, q = 0.f;
    const float* px = x + ((size_t)b * TT * FF + f) * 8 + ch;
    #pragma unroll 4
    for (int t = tl; t < TT; t += 32) {
        float v = px[(size_t)t * FF * 8];
        s += v; q += v * v;
    }
    s += __shfl_xor_sync(0xffffffffu, s, 8);
    q += __shfl_xor_sync(0xffffffffu, q, 8);
    s += __shfl_xor_sync(0xffffffffu, s, 16);
    q += __shfl_xor_sync(0xffffffffu, q, 16);

    __shared__ float sb[8][8], qb[8][8];
    int warp = tid >> 5, lane = tid & 31;
    if (lane < 8) { sb[warp][lane] = s; qb[warp][lane] = q; }
    __syncthreads();

    if (tid == 0) {
        const float invT = 1.0f / (float)TT;
        float ssum[8], qsum[8];
        #pragma unroll
        for (int c = 0; c < 8; c++) {
            float a = 0.f, bq = 0.f;
            #pragma unroll
            for (int w = 0; w < 8; w++) { a += sb[w][c]; bq += qb[w][c]; }
            ssum[c] = a * invT; qsum[c] = bq * invT;
        }
        float tot = 0.f;
        #pragma unroll
        for (int m = 0; m < 4; m++) {
            float mr = ssum[m], mi = ssum[m + 4];
            tot += qsum[m] + qsum[m + 4] - mr * mr - mi * mi;
        }
        #pragma unroll
        for (int j = 0; j < 8; j++) g_mean[(b * FF + f) * 8 + j] = ssum[j];
        g_inv[b * FF + f] = rsqrtf(fmaxf(tot, 1e-10f));
    }
}

// ---------------- K2: SCM pair features -> bf16 hi/lo ----------------
__global__ void feat_kernel(const float* __restrict__ x) {
    int bt = blockIdx.x;
    int b  = bt / TT;
    int tid = threadIdx.x;
    int fi = tid & 255, half = tid >> 8;

    const int ia[10] = {0,0,0,0,1,1,1,2,2,3};
    const int ja[10] = {0,1,2,3,1,2,3,2,3,3};

    for (int f = fi; f < FF; f += 256) {
        const float* px = x + ((size_t)bt * FF + f) * 8;
        const float* mn = g_mean + (b * FF + f) * 8;
        float inv = g_inv[b * FF + f];

        float vr[4], vi[4];
        #pragma unroll
        for (int m = 0; m < 4; m++) {
            vr[m] = (px[m]     - mn[m])     * inv;
            vi[m] = (px[m + 4] - mn[m + 4]) * inv;
        }
        float s1m = 1.0f - g_s1[f];
        float s2 = g_s2[f];

        size_t rowbase = (size_t)bt * C2P * XSP + f;
        #pragma unroll
        for (int pp = 0; pp < 5; pp++) {
            int p = 5 * half + pp;
            float re = vr[ia[p]] * vr[ja[p]] + vi[ia[p]] * vi[ja[p]];
            float im = vi[ia[p]] * vr[ja[p]] - vr[ia[p]] * vi[ja[p]];
            float a2 = re * re + im * im;
            float mag = (a2 > 0.f) ? exp2f(s1m * 0.5f * log2f(a2)) : 0.f;
            float ang  = atan2f(im, re) * s2;
            float sn, cs;
            sincosf(ang, &sn, &cs);
            float v0 = mag * cs, v1 = mag * sn;
            __nv_bfloat16 h0 = __float2bfloat16(v0);
            __nv_bfloat16 h1 = __float2bfloat16(v1);
            size_t r0 = rowbase + (size_t)(2 * p) * XSP;
            size_t r1 = r0 + XSP;
            g_xh[r0] = h0;
            g_xl[r0] = __float2bfloat16(v0 - __bfloat162float(h0));
            g_xh[r1] = h1;
            g_xl[r1] = __float2bfloat16(v1 - __bfloat162float(h1));
        }
    }
}

// ---------------- K3: HMMA bf16-split conv + LayerNorm ----------------
// 12 warps = 4 m-groups (m32) x 3 n-groups. Epilogue: STS y into smem
// (linear [d][f]) then coalesced float4 normalize+store pass.
extern __shared__ char sm[];

__global__ void __launch_bounds__(NTH, 1)
conv_ln_kernel(const float* __restrict__ conv_b,
               float* __restrict__ out) {
    int bt = blockIdx.x;
    int b  = bt / TT;
    int t  = bt % TT;
    int tid = threadIdx.x;
    int warp = tid >> 5, lane = tid & 31;
    int g = lane >> 2, tg = lane & 3;
    int mg = warp & 3;          // d rows [32mg, 32mg+32)
    int ng = warp >> 2;         // f cols [88ng, 88ng+88)

    uint32_t sb = smem_u32(sm);

    // ---- stage A via cp.async ----
    for (int i = tid * 16; i < 128*WSP*2; i += NTH * 16) {
        CP16(sb + WS_HI + i, (const char*)g_wa_hi + i);
        CP16(sb + WS_LO + i, (const char*)g_wa_lo + i);
    }

    // ---- stage B rows via cp.async (zero-fill invalid rows) ----
    for (int j = warp; j < KP; j += 12) {
        int c = j / 5, k = j - c * 5;
        int tt = t + k - 2;
        bool jv = (j < 100) && (tt >= 0) && (tt < TT);
        size_t ro = jv ? ((size_t)((b*TT + tt)*C2P + c) * XSP) * 2 : 0;
        const char* sh = (const char*)g_xh + ro;
        const char* sl = (const char*)g_xl + ro;
        uint32_t dh = sb + BS_HI + j * (BSP*2);
        uint32_t dl = sb + BS_LO + j * (BSP*2);
        int sz = jv ? 16 : 0;
        for (int ch = lane * 16; ch < BSP*2; ch += 32 * 16) {
            CP16Z(dh + ch, sh + ch, sz);
            CP16Z(dl + ch, sl + ch, sz);
        }
    }
    CPCOMMIT();
    CPWAITALL();
    __syncthreads();

    // ---- mainloop ----
    float acc[2][11][4];
    #pragma unroll
    for (int mt = 0; mt < 2; mt++)
        #pragma unroll
        for (int nt = 0; nt < 11; nt++)
            #pragma unroll
            for (int ci = 0; ci < 4; ci++) acc[mt][nt][ci] = 0.f;

    int aRow = (lane & 7) + 8 * ((lane >> 3) & 1);
    int aK   = (lane >> 4) * 8;
    uint32_t aoff = sb + WS_HI + (uint32_t)(((32*mg + aRow) * WSP + aK) * 2);
    int kRow = (lane & 7) + 8 * ((lane >> 3) & 1);
    uint32_t boff4 = sb + BS_HI
                   + (uint32_t)((kRow * BSP + 88*ng) * 2)
                   + (uint32_t)((lane >> 4) * 16);
    uint32_t boff2 = sb + BS_HI + (uint32_t)((kRow * BSP + 88*ng + 80) * 2);

    for (int kt = 0; kt < 7; kt++) {
        uint32_t ah[2][4], al[2][4];
        #pragma unroll
        for (int mt = 0; mt < 2; mt++) {
            uint32_t a = aoff + mt * (16*WSP*2) + kt * 32;
            LDSM4(ah[mt][0], ah[mt][1], ah[mt][2], ah[mt][3], a);
            LDSM4(al[mt][0], al[mt][1], al[mt][2], al[mt][3], a + (WS_LO - WS_HI));
        }
        uint32_t krowoff = kt * (16*BSP*2);
        #pragma unroll
        for (int np = 0; np < 5; np++) {
            uint32_t badr = boff4 + krowoff + np * 32;
            uint32_t bh[4], bl[4];
            LDSM4T(bh[0], bh[1], bh[2], bh[3], badr);
            LDSM4T(bl[0], bl[1], bl[2], bl[3], badr + (BS_LO - BS_HI));
            int nt = 2 * np;
            #pragma unroll
            for (int mt = 0; mt < 2; mt++) {
                MMABF16(acc[mt][nt],     ah[mt], bh[0], bh[1]);
                MMABF16(acc[mt][nt + 1], ah[mt], bh[2], bh[3]);
                MMABF16(acc[mt][nt],     ah[mt], bl[0], bl[1]);
                MMABF16(acc[mt][nt + 1], ah[mt], bl[2], bl[3]);
                MMABF16(acc[mt][nt],     al[mt], bh[0], bh[1]);
                MMABF16(acc[mt][nt + 1], al[mt], bh[2], bh[3]);
            }
        }
        {   // tail n-tile 10
            uint32_t badr = boff2 + krowoff;
            uint32_t bh0, bh1, bl0, bl1;
            LDSM2T(bh0, bh1, badr);
            LDSM2T(bl0, bl1, badr + (BS_LO - BS_HI));
            #pragma unroll
            for (int mt = 0; mt < 2; mt++) {
                MMABF16(acc[mt][10], ah[mt], bh0, bh1);
                MMABF16(acc[mt][10], ah[mt], bl0, bl1);
                MMABF16(acc[mt][10], al[mt], bh0, bh1);
            }
        }
    }
    __syncthreads();   // staging regions dead; reuse as y_s

    // ---- bias ----
    float bias[2][2];
    #pragma unroll
    for (int mt = 0; mt < 2; mt++) {
        int r = 32*mg + 16*mt + g;
        bias[mt][0] = conv_b[r];
        bias[mt][1] = conv_b[r + 8];
    }

    // ---- STS y (+bias) into linear smem [d][f] ----
    float* y_s = (float*)sm;
    #pragma unroll
    for (int mt = 0; mt < 2; mt++) {
        int r0 = (32*mg + 16*mt + g) * FF;
        int r1 = r0 + 8 * FF;
        #pragma unroll
        for (int nt = 0; nt < 11; nt++) {
            int fb = 88*ng + 8*nt + 2*tg;
            if (ng < 2 || fb < FF) {
                y_s[r0 + fb] = acc[mt][nt][0] + bias[mt][0];
                y_s[r1 + fb] = acc[mt][nt][2] + bias[mt][1];
            }
            if (ng < 2 || fb + 1 < FF) {
                y_s[r0 + fb + 1] = acc[mt][nt][1] + bias[mt][0];
                y_s[r1 + fb + 1] = acc[mt][nt][3] + bias[mt][1];
            }
        }
    }

    // ---- LN stats from registers (overlaps STS drain) ----
    float* red = (float*)(sm + SRED);
    float s = 0.f, q = 0.f;
    if (ng < 2) {
        #pragma unroll
        for (int mt = 0; mt < 2; mt++)
            #pragma unroll
            for (int nt = 0; nt < 11; nt++) {
                float v0 = acc[mt][nt][0] + bias[mt][0];
                float v1 = acc[mt][nt][1] + bias[mt][0];
                float v2 = acc[mt][nt][2] + bias[mt][1];
                float v3 = acc[mt][nt][3] + bias[mt][1];
                s += (v0 + v1) + (v2 + v3);
                q += (v0*v0 + v1*v1) + (v2*v2 + v3*v3);
            }
    } else {
        #pragma unroll
        for (int mt = 0; mt < 2; mt++)
            #pragma unroll
            for (int nt = 0; nt < 11; nt++) {
                int fb = 176 + 8*nt + 2*tg;
                if (fb < FF) {
                    float v0 = acc[mt][nt][0] + bias[mt][0];
                    float v2 = acc[mt][nt][2] + bias[mt][1];
                    s += v0 + v2; q += v0*v0 + v2*v2;
                }
                if (fb + 1 < FF) {
                    float v1 = acc[mt][nt][1] + bias[mt][0];
                    float v3 = acc[mt][nt][3] + bias[mt][1];
                    s += v1 + v3; q += v1*v1 + v3*v3;
                }
            }
    }
    #pragma unroll
    for (int o = 16; o > 0; o >>= 1) {
        s += __shfl_xor_sync(0xffffffffu, s, o);
        q += __shfl_xor_sync(0xffffffffu, q, o);
    }
    if (lane == 0) { red[warp] = s; red[12 + warp] = q; }
    __syncthreads();
    if (tid < 32) {
        s = (tid < 12) ? red[tid] : 0.f;
        q = (tid < 12) ? red[12 + tid] : 0.f;
        #pragma unroll
        for (int o = 8; o > 0; o >>= 1) {
            s += __shfl_xor_sync(0xffffffffu, s, o);
            q += __shfl_xor_sync(0xffffffffu, q, o);
        }
        if (tid == 0) {
            const float invN = 1.0f / (float)NLN;
            float mu  = s * invN;
            float var = q * invN - mu * mu;
            red[24] = mu;
            red[25] = rsqrtf(var + 1e-5f);
        }
    }
    __syncthreads();
    float mu = red[24], rs = red[25];

    // ---- coalesced normalize + store (float4) ----
    const float4* y4 = (const float4*)y_s;
    const uint4*  w4 = (const uint4*)g_lnwb;
    float4* o4 = (float4*)(out + (size_t)bt * NLN);
    for (int i = tid; i < NLN / 4; i += NTH) {
        float4 y = y4[i];
        uint4  w = w4[i];
        float4 r;
        r.x = (y.x - mu) * rs * bf16lo(w.x) + bf16hi(w.x);
        r.y = (y.y - mu) * rs * bf16lo(w.y) + bf16hi(w.y);
        r.z = (y.z - mu) * rs * bf16lo(w.z) + bf16hi(w.z);
        r.w = (y.w - mu) * rs * bf16lo(w.w) + bf16hi(w.w);
        o4[i] = r;
    }
}

// ---------------- launch ----------------
extern "C" void kernel_launch(void* const* d_in, const int* in_sizes, int n_in,
                              void* d_out, int out_size) {
    const float* x    = (const float*)d_in[0];
    const float* expo = (const float*)d_in[1];
    const float* ipd  = (const float*)d_in[2];
    const float* cw   = (const float*)d_in[3];
    const float* cb   = (const float*)d_in[4];
    const float* lw   = (const float*)d_in[5];
    const float* lb   = (const float*)d_in[6];
    float* out = (float*)d_out;

    wsplit_kernel<<<1, 256>>>(cw);
    lnpack_kernel<<<(NLN + 511) / 512, 512>>>(lw, lb, expo, ipd);
    stats_kernel<<<dim3(BB, FF), 256>>>(x);
    feat_kernel<<<BB * TT, 512>>>(x);

    cudaFuncSetAttribute(conv_ln_kernel,
                         cudaFuncAttributeMaxDynamicSharedMemorySize, SM_TOTAL);
    conv_ln_kernel<<<BB * TT, NTH, SM_TOTAL>>>(cb, out);
}

// round 17
// speedup vs baseline: 2.0591x; 1.0005x over previous
#include <cuda_runtime.h>
#include <cuda_bf16.h>
#include <math.h>
#include <stdint.h>

#define BB 4
#define TT 512
#define FF 257
#define DD 128
#define C2P 20
#define NLN (DD*FF)
#define NTH 384

#define KP   112
#define WSP  120           // A pitch (bf16): 240B rows
#define BSP  264           // B pitch (elements): 528B rows (33x16B)
#define XSP  264           // g_xh/g_xl row pitch (elements)

// smem byte offsets
#define WS_HI 0
#define WS_LO (WS_HI + 128*WSP*2)      // 30720
#define BS_HI (WS_LO + 128*WSP*2)      // 61440
#define BS_LO (BS_HI + KP*BSP*2)       // 120576
#define BS_END (BS_LO + KP*BSP*2)      // 179712
#define SRED  BS_END                   // red buffer beyond staging
#define SM_TOTAL (SRED + 224)          // 179936
// y_s (128*257 floats = 131584 B) reuses [0, 131584) after mainloop

#define LDSM4(r0,r1,r2,r3,addr) \
  asm volatile("ldmatrix.sync.aligned.m8n8.x4.shared.b16 {%0,%1,%2,%3}, [%4];" \
    : "=r"(r0),"=r"(r1),"=r"(r2),"=r"(r3) : "r"(addr))
#define LDSM4T(r0,r1,r2,r3,addr) \
  asm volatile("ldmatrix.sync.aligned.m8n8.x4.trans.shared.b16 {%0,%1,%2,%3}, [%4];" \
    : "=r"(r0),"=r"(r1),"=r"(r2),"=r"(r3) : "r"(addr))
#define LDSM2T(r0,r1,addr) \
  asm volatile("ldmatrix.sync.aligned.m8n8.x2.trans.shared.b16 {%0,%1}, [%2];" \
    : "=r"(r0),"=r"(r1) : "r"(addr))
#define MMABF16(c,a,b0,b1) \
  asm volatile("mma.sync.aligned.m16n8k16.row.col.f32.bf16.bf16.f32 " \
    "{%0,%1,%2,%3}, {%4,%5,%6,%7}, {%8,%9}, {%0,%1,%2,%3};" \
    : "+f"((c)[0]),"+f"((c)[1]),"+f"((c)[2]),"+f"((c)[3]) \
    : "r"((a)[0]),"r"((a)[1]),"r"((a)[2]),"r"((a)[3]),"r"(b0),"r"(b1))

#define CP16(d,s)    asm volatile("cp.async.cg.shared.global [%0], [%1], 16;" :: "r"(d), "l"(s) : "memory")
#define CP16Z(d,s,z) asm volatile("cp.async.cg.shared.global [%0], [%1], 16, %2;" :: "r"(d), "l"(s), "r"(z) : "memory")
#define CPCOMMIT()   asm volatile("cp.async.commit_group;" ::: "memory")
#define CPWAITALL()  asm volatile("cp.async.wait_group 0;" ::: "memory")

__device__ __forceinline__ uint32_t smem_u32(const void* p) {
    uint32_t a;
    asm("{ .reg .u64 t; cvta.to.shared.u64 t, %1; cvt.u32.u64 %0, t; }" : "=r"(a) : "l"(p));
    return a;
}
__device__ __forceinline__ float bf16lo(uint32_t u) {
    return __bfloat162float(__ushort_as_bfloat16((unsigned short)(u & 0xffffu)));
}
__device__ __forceinline__ float bf16hi(uint32_t u) {
    return __bfloat162float(__ushort_as_bfloat16((unsigned short)(u >> 16)));
}

// ---------------- device scratch ----------------
__device__ float g_mean[BB*FF*8];
__device__ float g_inv[BB*FF];
__device__ float g_s1[FF];
__device__ float g_s2[FF];
__device__ __align__(16) __nv_bfloat16 g_wa_hi[128*WSP];
__device__ __align__(16) __nv_bfloat16 g_wa_lo[128*WSP];
__device__ __align__(16) uint32_t g_lnwb[NLN];
__device__ __align__(16) __nv_bfloat16 g_xh[(size_t)BB*TT*C2P*XSP];
__device__ __align__(16) __nv_bfloat16 g_xl[(size_t)BB*TT*C2P*XSP];

// ---------------- K0a: weight split ----------------
__global__ void wsplit_kernel(const float* __restrict__ conv_w) {
    for (int i = threadIdx.x; i < 128*WSP; i += blockDim.x) {
        int d = i / WSP, j = i - d*WSP;
        float v = (j < 100) ? conv_w[d*100 + j] : 0.f;
        __nv_bfloat16 h = __float2bfloat16(v);
        __nv_bfloat16 l = __float2bfloat16(v - __bfloat162float(h));
        g_wa_hi[i] = h;
        g_wa_lo[i] = l;
    }
}

// ---------------- K0b: ln param pack + sigmoids ----------------
__global__ void lnpack_kernel(const float* __restrict__ lw,
                              const float* __restrict__ lb,
                              const float* __restrict__ expo,
                              const float* __restrict__ ipd) {
    int i = blockIdx.x * blockDim.x + threadIdx.x;
    if (i < NLN) {
        unsigned short w = __bfloat16_as_ushort(__float2bfloat16(lw[i]));
        unsigned short b = __bfloat16_as_ushort(__float2bfloat16(lb[i]));
        g_lnwb[i] = (uint32_t)w | ((uint32_t)b << 16);
    }
    if (i < FF) {
        g_s1[i] = 1.0f / (1.0f + expf(-expo[i]));
        g_s2[i] = 1.0f / (1.0f + expf(-ipd[i]));
    }
}

// ---------------- K1: time stats ----------------
__global__ void stats_kernel(const float* __restrict__ x) {
    int b = blockIdx.x;
    int f = blockIdx.y;
    int tid = threadIdx.x;
    int ch = tid & 7;
    int tl = tid >> 3;

    float s = 0.f, q = 0.f;
    const float* px = x + ((size_t)b * TT * FF + f) * 8 + ch;
    #pragma unroll 4
    for (int t = tl; t < TT; t += 32) {
        float v = px[(size_t)t * FF * 8];
        s += v; q += v * v;
    }
    s += __shfl_xor_sync(0xffffffffu, s, 8);
    q += __shfl_xor_sync(0xffffffffu, q, 8);
    s += __shfl_xor_sync(0xffffffffu, s, 16);
    q += __shfl_xor_sync(0xffffffffu, q, 16);

    __shared__ float sb[8][8], qb[8][8];
    int warp = tid >> 5, lane = tid & 31;
    if (lane < 8) { sb[warp][lane] = s; qb[warp][lane] = q; }
    __syncthreads();

    if (tid == 0) {
        const float invT = 1.0f / (float)TT;
        float ssum[8], qsum[8];
        #pragma unroll
        for (int c = 0; c < 8; c++) {
            float a = 0.f, bq = 0.f;
            #pragma unroll
            for (int w = 0; w < 8; w++) { a += sb[w][c]; bq += qb[w][c]; }
            ssum[c] = a * invT; qsum[c] = bq * invT;
        }
        float tot = 0.f;
        #pragma unroll
        for (int m = 0; m < 4; m++) {
            float mr = ssum[m], mi = ssum[m + 4];
            tot += qsum[m] + qsum[m + 4] - mr * mr - mi * mi;
        }
        #pragma unroll
        for (int j = 0; j < 8; j++) g_mean[(b * FF + f) * 8 + j] = ssum[j];
        g_inv[b * FF + f] = rsqrtf(fmaxf(tot, 1e-10f));
    }
}

// ---------------- K2: SCM pair features -> bf16 hi/lo ----------------
__global__ void feat_kernel(const float* __restrict__ x) {
    int bt = blockIdx.x;
    int b  = bt / TT;
    int tid = threadIdx.x;
    int fi = tid & 255, half = tid >> 8;

    const int ia[10] = {0,0,0,0,1,1,1,2,2,3};
    const int ja[10] = {0,1,2,3,1,2,3,2,3,3};

    for (int f = fi; f < FF; f += 256) {
        const float* px = x + ((size_t)bt * FF + f) * 8;
        const float* mn = g_mean + (b * FF + f) * 8;
        float inv = g_inv[b * FF + f];

        float vr[4], vi[4];
        #pragma unroll
        for (int m = 0; m < 4; m++) {
            vr[m] = (px[m]     - mn[m])     * inv;
            vi[m] = (px[m + 4] - mn[m + 4]) * inv;
        }
        float s1m = 1.0f - g_s1[f];
        float s2 = g_s2[f];

        size_t rowbase = (size_t)bt * C2P * XSP + f;
        #pragma unroll
        for (int pp = 0; pp < 5; pp++) {
            int p = 5 * half + pp;
            float re = vr[ia[p]] * vr[ja[p]] + vi[ia[p]] * vi[ja[p]];
            float im = vi[ia[p]] * vr[ja[p]] - vr[ia[p]] * vi[ja[p]];
            float a2 = re * re + im * im;
            float mag = (a2 > 0.f) ? exp2f(s1m * 0.5f * log2f(a2)) : 0.f;
            float ang  = atan2f(im, re) * s2;
            float sn, cs;
            sincosf(ang, &sn, &cs);
            float v0 = mag * cs, v1 = mag * sn;
            __nv_bfloat16 h0 = __float2bfloat16(v0);
            __nv_bfloat16 h1 = __float2bfloat16(v1);
            size_t r0 = rowbase + (size_t)(2 * p) * XSP;
            size_t r1 = r0 + XSP;
            g_xh[r0] = h0;
            g_xl[r0] = __float2bfloat16(v0 - __bfloat162float(h0));
            g_xh[r1] = h1;
            g_xl[r1] = __float2bfloat16(v1 - __bfloat162float(h1));
        }
    }
}

// ---------------- K3: HMMA bf16-split conv + LayerNorm ----------------
// 12 warps = 4 m-groups (m32) x 3 n-groups. Epilogue: STS y into smem
// (linear [d][f]) then coalesced float4 normalize+store pass.
extern __shared__ char sm[];

__global__ void __launch_bounds__(NTH, 1)
conv_ln_kernel(const float* __restrict__ conv_b,
               float* __restrict__ out) {
    int bt = blockIdx.x;
    int b  = bt / TT;
    int t  = bt % TT;
    int tid = threadIdx.x;
    int warp = tid >> 5, lane = tid & 31;
    int g = lane >> 2, tg = lane & 3;
    int mg = warp & 3;          // d rows [32mg, 32mg+32)
    int ng = warp >> 2;         // f cols [88ng, 88ng+88)

    uint32_t sb = smem_u32(sm);

    // ---- stage A via cp.async ----
    for (int i = tid * 16; i < 128*WSP*2; i += NTH * 16) {
        CP16(sb + WS_HI + i, (const char*)g_wa_hi + i);
        CP16(sb + WS_LO + i, (const char*)g_wa_lo + i);
    }

    // ---- stage B rows via cp.async (zero-fill invalid rows) ----
    for (int j = warp; j < KP; j += 12) {
        int c = j / 5, k = j - c * 5;
        int tt = t + k - 2;
        bool jv = (j < 100) && (tt >= 0) && (tt < TT);
        size_t ro = jv ? ((size_t)((b*TT + tt)*C2P + c) * XSP) * 2 : 0;
        const char* sh = (const char*)g_xh + ro;
        const char* sl = (const char*)g_xl + ro;
        uint32_t dh = sb + BS_HI + j * (BSP*2);
        uint32_t dl = sb + BS_LO + j * (BSP*2);
        int sz = jv ? 16 : 0;
        for (int ch = lane * 16; ch < BSP*2; ch += 32 * 16) {
            CP16Z(dh + ch, sh + ch, sz);
            CP16Z(dl + ch, sl + ch, sz);
        }
    }
    CPCOMMIT();
    CPWAITALL();
    __syncthreads();

    // ---- mainloop ----
    float acc[2][11][4];
    #pragma unroll
    for (int mt = 0; mt < 2; mt++)
        #pragma unroll
        for (int nt = 0; nt < 11; nt++)
            #pragma unroll
            for (int ci = 0; ci < 4; ci++) acc[mt][nt][ci] = 0.f;

    int aRow = (lane & 7) + 8 * ((lane >> 3) & 1);
    int aK   = (lane >> 4) * 8;
    uint32_t aoff = sb + WS_HI + (uint32_t)(((32*mg + aRow) * WSP + aK) * 2);
    int kRow = (lane & 7) + 8 * ((lane >> 3) & 1);
    uint32_t boff4 = sb + BS_HI
                   + (uint32_t)((kRow * BSP + 88*ng) * 2)
                   + (uint32_t)((lane >> 4) * 16);
    uint32_t boff2 = sb + BS_HI + (uint32_t)((kRow * BSP + 88*ng + 80) * 2);

    for (int kt = 0; kt < 7; kt++) {
        uint32_t ah[2][4], al[2][4];
        #pragma unroll
        for (int mt = 0; mt < 2; mt++) {
            uint32_t a = aoff + mt * (16*WSP*2) + kt * 32;
            LDSM4(ah[mt][0], ah[mt][1], ah[mt][2], ah[mt][3], a);
            LDSM4(al[mt][0], al[mt][1], al[mt][2], al[mt][3], a + (WS_LO - WS_HI));
        }
        uint32_t krowoff = kt * (16*BSP*2);
        #pragma unroll
        for (int np = 0; np < 5; np++) {
            uint32_t badr = boff4 + krowoff + np * 32;
            uint32_t bh[4], bl[4];
            LDSM4T(bh[0], bh[1], bh[2], bh[3], badr);
            LDSM4T(bl[0], bl[1], bl[2], bl[3], badr + (BS_LO - BS_HI));
            int nt = 2 * np;
            #pragma unroll
            for (int mt = 0; mt < 2; mt++) {
                MMABF16(acc[mt][nt],     ah[mt], bh[0], bh[1]);
                MMABF16(acc[mt][nt + 1], ah[mt], bh[2], bh[3]);
                MMABF16(acc[mt][nt],     ah[mt], bl[0], bl[1]);
                MMABF16(acc[mt][nt + 1], ah[mt], bl[2], bl[3]);
                MMABF16(acc[mt][nt],     al[mt], bh[0], bh[1]);
                MMABF16(acc[mt][nt + 1], al[mt], bh[2], bh[3]);
            }
        }
        {   // tail n-tile 10
            uint32_t badr = boff2 + krowoff;
            uint32_t bh0, bh1, bl0, bl1;
            LDSM2T(bh0, bh1, badr);
            LDSM2T(bl0, bl1, badr + (BS_LO - BS_HI));
            #pragma unroll
            for (int mt = 0; mt < 2; mt++) {
                MMABF16(acc[mt][10], ah[mt], bh0, bh1);
                MMABF16(acc[mt][10], ah[mt], bl0, bl1);
                MMABF16(acc[mt][10], al[mt], bh0, bh1);
            }
        }
    }
    __syncthreads();   // staging regions dead; reuse as y_s

    // ---- bias ----
    float bias[2][2];
    #pragma unroll
    for (int mt = 0; mt < 2; mt++) {
        int r = 32*mg + 16*mt + g;
        bias[mt][0] = conv_b[r];
        bias[mt][1] = conv_b[r + 8];
    }

    // ---- STS y (+bias) into linear smem [d][f] ----
    float* y_s = (float*)sm;
    #pragma unroll
    for (int mt = 0; mt < 2; mt++) {
        int r0 = (32*mg + 16*mt + g) * FF;
        int r1 = r0 + 8 * FF;
        #pragma unroll
        for (int nt = 0; nt < 11; nt++) {
            int fb = 88*ng + 8*nt + 2*tg;
            if (ng < 2 || fb < FF) {
                y_s[r0 + fb] = acc[mt][nt][0] + bias[mt][0];
                y_s[r1 + fb] = acc[mt][nt][2] + bias[mt][1];
            }
            if (ng < 2 || fb + 1 < FF) {
                y_s[r0 + fb + 1] = acc[mt][nt][1] + bias[mt][0];
                y_s[r1 + fb + 1] = acc[mt][nt][3] + bias[mt][1];
            }
        }
    }

    // ---- LN stats from registers (overlaps STS drain) ----
    float* red = (float*)(sm + SRED);
    float s = 0.f, q = 0.f;
    if (ng < 2) {
        #pragma unroll
        for (int mt = 0; mt < 2; mt++)
            #pragma unroll
            for (int nt = 0; nt < 11; nt++) {
                float v0 = acc[mt][nt][0] + bias[mt][0];
                float v1 = acc[mt][nt][1] + bias[mt][0];
                float v2 = acc[mt][nt][2] + bias[mt][1];
                float v3 = acc[mt][nt][3] + bias[mt][1];
                s += (v0 + v1) + (v2 + v3);
                q += (v0*v0 + v1*v1) + (v2*v2 + v3*v3);
            }
    } else {
        #pragma unroll
        for (int mt = 0; mt < 2; mt++)
            #pragma unroll
            for (int nt = 0; nt < 11; nt++) {
                int fb = 176 + 8*nt + 2*tg;
                if (fb < FF) {
                    float v0 = acc[mt][nt][0] + bias[mt][0];
                    float v2 = acc[mt][nt][2] + bias[mt][1];
                    s += v0 + v2; q += v0*v0 + v2*v2;
                }
                if (fb + 1 < FF) {
                    float v1 = acc[mt][nt][1] + bias[mt][0];
                    float v3 = acc[mt][nt][3] + bias[mt][1];
                    s += v1 + v3; q += v1*v1 + v3*v3;
                }
            }
    }
    #pragma unroll
    for (int o = 16; o > 0; o >>= 1) {
        s += __shfl_xor_sync(0xffffffffu, s, o);
        q += __shfl_xor_sync(0xffffffffu, q, o);
    }
    if (lane == 0) { red[warp] = s; red[12 + warp] = q; }
    __syncthreads();
    if (tid < 32) {
        s = (tid < 12) ? red[tid] : 0.f;
        q = (tid < 12) ? red[12 + tid] : 0.f;
        #pragma unroll
        for (int o = 8; o > 0; o >>= 1) {
            s += __shfl_xor_sync(0xffffffffu, s, o);
            q += __shfl_xor_sync(0xffffffffu, q, o);
        }
        if (tid == 0) {
            const float invN = 1.0f / (float)NLN;
            float mu  = s * invN;
            float var = q * invN - mu * mu;
            red[24] = mu;
            red[25] = rsqrtf(var + 1e-5f);
        }
    }
    __syncthreads();
    float mu = red[24], rs = red[25];

    // ---- coalesced normalize + store (float4) ----
    const float4* y4 = (const float4*)y_s;
    const uint4*  w4 = (const uint4*)g_lnwb;
    float4* o4 = (float4*)(out + (size_t)bt * NLN);
    for (int i = tid; i < NLN / 4; i += NTH) {
        float4 y = y4[i];
        uint4  w = w4[i];
        float4 r;
        r.x = (y.x - mu) * rs * bf16lo(w.x) + bf16hi(w.x);
        r.y = (y.y - mu) * rs * bf16lo(w.y) + bf16hi(w.y);
        r.z = (y.z - mu) * rs * bf16lo(w.z) + bf16hi(w.z);
        r.w = (y.w - mu) * rs * bf16lo(w.w) + bf16hi(w.w);
        o4[i] = r;
    }
}

// ---------------- launch ----------------
extern "C" void kernel_launch(void* const* d_in, const int* in_sizes, int n_in,
                              void* d_out, int out_size) {
    const float* x    = (const float*)d_in[0];
    const float* expo = (const float*)d_in[1];
    const float* ipd  = (const float*)d_in[2];
    const float* cw   = (const float*)d_in[3];
    const float* cb   = (const float*)d_in[4];
    const float* lw   = (const float*)d_in[5];
    const float* lb   = (const float*)d_in[6];
    float* out = (float*)d_out;

    wsplit_kernel<<<1, 256>>>(cw);
    lnpack_kernel<<<(NLN + 511) / 512, 512>>>(lw, lb, expo, ipd);
    stats_kernel<<<dim3(BB, FF), 256>>>(x);
    feat_kernel<<<BB * TT, 512>>>(x);

    cudaFuncSetAttribute(conv_ln_kernel,
                         cudaFuncAttributeMaxDynamicSharedMemorySize, SM_TOTAL);
    conv_ln_kernel<<<BB * TT, NTH, SM_TOTAL>>>(cb, out);
}